// round 9
// baseline (speedup 1.0000x reference)
#include <cuda_runtime.h>
#include <cuda_bf16.h>
#include <cstdint>

#define N_NODES 20000
#define N_EDGES 320000
#define D 256
#define NB 79          // ceil(20000/256) scan blocks

// ---------------- scratch (no allocations allowed) ----------------
// A' = [hi(aggr)|hi(x)|lo(aggr)|lo(x)] per row: 1024 bf16 cols
__device__ __nv_bfloat16 g_Ahl[(size_t)N_NODES * 1024];
// W' = [hi(Wl)|hi(Wr)|lo(Wl)|lo(Wr)] per output col: 1024 bf16 cols
__device__ __nv_bfloat16 g_Whl[256 * 1024];
__device__ int g_count[N_NODES];
__device__ int g_off[N_NODES + 1];
__device__ int g_cursor[N_NODES];
__device__ int g_srclist[N_EDGES];
__device__ int g_bsum[NB];
__device__ int g_is64;

// ---------------- helpers ----------------
__device__ __forceinline__ uint32_t smem_u32(const void* p) {
    uint32_t a;
    asm("{ .reg .u64 t; cvta.to.shared.u64 t, %1; cvt.u32.u64 %0, t; }"
        : "=r"(a) : "l"(p));
    return a;
}
__device__ __forceinline__ void split_bf16(float v, __nv_bfloat16& hi, __nv_bfloat16& lo) {
    hi = __float2bfloat16(v);
    lo = __float2bfloat16(v - __bfloat162float(hi));
}
__device__ __forceinline__ void cp16(uint32_t dst, const void* src, int srcsz) {
    asm volatile("cp.async.cg.shared.global [%0], [%1], 16, %2;"
                 :: "r"(dst), "l"(src), "r"(srcsz));
}
__device__ __forceinline__ void cp_commit() { asm volatile("cp.async.commit_group;" ::: "memory"); }
__device__ __forceinline__ void cp_wait1()  { asm volatile("cp.async.wait_group 1;" ::: "memory"); }
__device__ __forceinline__ void cp_wait0()  { asm volatile("cp.async.wait_group 0;" ::: "memory"); }

__device__ __forceinline__ void ldm_x4(uint32_t* r, uint32_t addr) {
    asm volatile("ldmatrix.sync.aligned.m8n8.x4.shared.b16 {%0,%1,%2,%3}, [%4];"
                 : "=r"(r[0]), "=r"(r[1]), "=r"(r[2]), "=r"(r[3]) : "r"(addr));
}
__device__ __forceinline__ void mma16816(float* d, const uint32_t* a, const uint32_t* b) {
    asm volatile("mma.sync.aligned.m16n8k16.row.col.f32.bf16.bf16.f32 "
                 "{%0,%1,%2,%3}, {%4,%5,%6,%7}, {%8,%9}, {%0,%1,%2,%3};"
                 : "+f"(d[0]), "+f"(d[1]), "+f"(d[2]), "+f"(d[3])
                 : "r"(a[0]), "r"(a[1]), "r"(a[2]), "r"(a[3]), "r"(b[0]), "r"(b[1]));
}

// ---------------- init: zero counts + warp-parallel dtype sniff ----------------
__global__ void init_kernel(const int* __restrict__ ei) {
    int idx = blockIdx.x * 256 + threadIdx.x;
    if (idx < N_NODES) { g_count[idx] = 0; g_cursor[idx] = 0; }
    if (idx == 0) g_off[N_NODES] = N_EDGES;
    if (blockIdx.x == 0 && threadIdx.x < 32) {
        int nz = 0;
        for (int i = threadIdx.x; i < 512; i += 32)
            nz |= (ei[2 * i + 1] != 0);
        unsigned m = __ballot_sync(0xffffffffu, nz);
        if (threadIdx.x == 0) g_is64 = (m == 0);
    }
}

__global__ void count_kernel(const int* __restrict__ ei) {
    int e = blockIdx.x * blockDim.x + threadIdx.x;
    if (e < N_EDGES) {
        int dst = g_is64 ? ei[2 * (N_EDGES + e)] : ei[N_EDGES + e];
        atomicAdd(&g_count[dst], 1);
    }
}

// ---------------- hierarchical scan ----------------
__global__ void partsum_kernel() {
    __shared__ int s[256];
    int tid = threadIdx.x;
    int idx = blockIdx.x * 256 + tid;
    s[tid] = (idx < N_NODES) ? g_count[idx] : 0;
    __syncthreads();
    for (int o = 128; o > 0; o >>= 1) {
        if (tid < o) s[tid] += s[tid + o];
        __syncthreads();
    }
    if (tid == 0) g_bsum[blockIdx.x] = s[0];
}

__global__ void scanwrite_kernel() {
    __shared__ int bs[128];
    __shared__ int sc[256];
    int tid = threadIdx.x;
    int b = blockIdx.x;
    if (tid < 128) bs[tid] = (tid < NB) ? g_bsum[tid] : 0;
    __syncthreads();
    for (int o = 1; o < 128; o <<= 1) {
        int v = (tid < 128 && tid >= o) ? bs[tid - o] : 0;
        __syncthreads();
        if (tid < 128) bs[tid] += v;
        __syncthreads();
    }
    int bp = (b == 0) ? 0 : bs[b - 1];
    int idx = b * 256 + tid;
    int cnt = (idx < N_NODES) ? g_count[idx] : 0;
    sc[tid] = cnt;
    __syncthreads();
    for (int o = 1; o < 256; o <<= 1) {
        int v = (tid >= o) ? sc[tid - o] : 0;
        __syncthreads();
        sc[tid] += v;
        __syncthreads();
    }
    if (idx < N_NODES) g_off[idx] = bp + sc[tid] - cnt;
}

__global__ void fill_kernel(const int* __restrict__ ei) {
    int e = blockIdx.x * blockDim.x + threadIdx.x;
    if (e >= N_EDGES) return;
    int src, dst;
    if (g_is64) { src = ei[2 * e]; dst = ei[2 * (N_EDGES + e)]; }
    else        { src = ei[e];     dst = ei[N_EDGES + e]; }
    int pos = atomicAdd(&g_cursor[dst], 1);
    g_srclist[g_off[dst] + pos] = src;
}

// ---------------- side-stream converters ----------------
__global__ void conv_x_kernel(const float* __restrict__ x) {
    int n = blockIdx.x;
    int c = threadIdx.x;
    float v = x[(size_t)n * D + c];
    __nv_bfloat16 hi, lo;
    split_bf16(v, hi, lo);
    g_Ahl[(size_t)n * 1024 + 256 + c] = hi;
    g_Ahl[(size_t)n * 1024 + 768 + c] = lo;
}

__global__ void conv_w_kernel(const float* __restrict__ Wl, const float* __restrict__ Wr) {
    int n = blockIdx.x;
    int c = threadIdx.x;
    __nv_bfloat16 hi, lo;
    split_bf16(Wl[n * D + c], hi, lo);
    g_Whl[n * 1024 + c] = hi;       g_Whl[n * 1024 + 512 + c] = lo;
    split_bf16(Wr[n * D + c], hi, lo);
    g_Whl[n * 1024 + 256 + c] = hi; g_Whl[n * 1024 + 768 + c] = lo;
}

// ---------------- aggregation (pure) ----------------
#define AGG_TILE 64
__global__ void aggregate_kernel(const float* __restrict__ x) {
    int n = blockIdx.x;
    int c = threadIdx.x;
    __shared__ int ssrc[AGG_TILE];
    int off0 = g_off[n];
    int off1 = g_off[n + 1];
    float sum = 0.f;
    for (int base = off0; base < off1; base += AGG_TILE) {
        int cnt = min(AGG_TILE, off1 - base);
        __syncthreads();
        if (c < cnt) ssrc[c] = g_srclist[base + c];
        __syncthreads();
#pragma unroll 8
        for (int i = 0; i < cnt; i++)
            sum += __ldg(&x[(size_t)ssrc[i] * D + c]);
    }
    float m = sum * (1.0f / fmaxf((float)(off1 - off0), 1.0f));
    __nv_bfloat16 hi, lo;
    split_bf16(m, hi, lo);
    g_Ahl[(size_t)n * 1024 + c] = hi;
    g_Ahl[(size_t)n * 1024 + 512 + c] = lo;
}

// ---------------- mma.sync bf16 partial GEMMs ----------------
// Each partial: 3 passes x 4 K-chunks of 64 (K=768 effective).
// XPART: out = x-terms + bias.  !XPART: out += aggr-terms.
#define GT 256
#define SM_BIAS   0
#define SM_TILES  1024
#define SM_A(b)   (SM_TILES + (b) * 32768)
#define SM_B(b)   (SM_TILES + (b) * 32768 + 16384)
#define GEMM_SMEM (SM_TILES + 65536)

extern __shared__ char sm_dyn[];

__device__ __forceinline__ void stage_chunk(uint32_t sb, int b, int Acol, int Wcol, int kc,
                                            int row0, int col0, int tid) {
    uint32_t smA = sb + SM_A(b), smB = sb + SM_B(b);
    const char* Abase = (const char*)g_Ahl;
    const char* Bbase = (const char*)g_Whl;
#pragma unroll
    for (int it = 0; it < 4; it++) {
        int u = it * GT + tid;              // 0..1023
        int r  = u >> 3;                    // row 0..127
        int ck = u & 7;                     // 16B chunk 0..7
        uint32_t swo = (uint32_t)(r * 8 + (ck ^ (r & 7))) * 16;
        int grow = row0 + r;
        int ok = (grow < N_NODES);
        const char* asrc = Abase + ((size_t)(ok ? grow : 0) * 1024 + Acol + kc + ck * 8) * 2;
        cp16(smA + swo, asrc, ok ? 16 : 0);
        const char* bsrc = Bbase + ((size_t)(col0 + r) * 1024 + Wcol + kc + ck * 8) * 2;
        cp16(smB + swo, bsrc, 16);
    }
    cp_commit();
}

template <bool XPART>
__global__ void __launch_bounds__(GT, 2)
gemm_part_kernel(const float* __restrict__ br, float* __restrict__ out) {
    uint32_t sb = smem_u32(sm_dyn);
    int tid  = threadIdx.x;
    int wid  = tid >> 5;
    int lane = tid & 31;
    int row0 = blockIdx.x * 128;
    int col0 = blockIdx.y * 128;
    int m0w  = (wid & 1) * 64;
    int n0w  = (wid >> 1) * 32;

    // term tables: hi*hi, hi*lo, lo*hi
    const int AO0 = XPART ? 256 : 0,   AO1 = XPART ? 256 : 0,   AO2 = XPART ? 768 : 512;
    const int WO0 = XPART ? 256 : 0,   WO1 = XPART ? 768 : 512, WO2 = XPART ? 256 : 0;

    float* sBias = (float*)(sm_dyn + SM_BIAS);
    if (XPART && tid < 256) sBias[tid] = br[tid];

    float acc[4][4][4];
#pragma unroll
    for (int mt = 0; mt < 4; mt++)
#pragma unroll
        for (int nt = 0; nt < 4; nt++)
#pragma unroll
            for (int j = 0; j < 4; j++) acc[mt][nt][j] = 0.f;

    int a_m  = m0w + (lane & 15);
    int a_kh = (lane >> 4);
    int b_n  = n0w + (lane & 7) + ((lane >> 4) & 1) * 8;
    int b_kh = (lane >> 3) & 1;

    const int CH = 12;
#pragma unroll 1
    for (int c = 0; c <= CH; c++) {
        if (c < CH) {
            int p  = c >> 2;
            int kc = (c & 3) * 64;
            int Ac = (p == 0) ? AO0 : (p == 1) ? AO1 : AO2;
            int Wc = (p == 0) ? WO0 : (p == 1) ? WO1 : WO2;
            stage_chunk(sb, c & 1, Ac, Wc, kc, row0, col0, tid);
        }
        if (c == 0) continue;
        int b = (c - 1) & 1;
        if (c < CH) cp_wait1(); else cp_wait0();
        __syncthreads();

        uint32_t smA = sb + SM_A(b), smB = sb + SM_B(b);
#pragma unroll
        for (int ks = 0; ks < 4; ks++) {
            uint32_t afrag[4][4], bfrag[4][4];
            int ka = ks * 2 + a_kh;
            int kb = ks * 2 + b_kh;
#pragma unroll
            for (int mt = 0; mt < 4; mt++) {
                int m = a_m + mt * 16;
                ldm_x4(afrag[mt], smA + (uint32_t)(m * 8 + (ka ^ (m & 7))) * 16);
            }
#pragma unroll
            for (int np = 0; np < 2; np++) {
                int n = b_n + np * 16;
                uint32_t r4[4];
                ldm_x4(r4, smB + (uint32_t)(n * 8 + (kb ^ (n & 7))) * 16);
                bfrag[np * 2][0]     = r4[0]; bfrag[np * 2][1]     = r4[1];
                bfrag[np * 2 + 1][0] = r4[2]; bfrag[np * 2 + 1][1] = r4[3];
            }
#pragma unroll
            for (int mt = 0; mt < 4; mt++)
#pragma unroll
                for (int nt = 0; nt < 4; nt++)
                    mma16816(acc[mt][nt], afrag[mt], bfrag[nt]);
        }
        __syncthreads();
    }

    int cr = lane >> 2;
    int cc = (lane & 3) * 2;
#pragma unroll
    for (int mt = 0; mt < 4; mt++) {
        int r0g = row0 + m0w + mt * 16 + cr;
#pragma unroll
        for (int nt = 0; nt < 4; nt++) {
            int colg = col0 + n0w + nt * 8 + cc;
#pragma unroll
            for (int h = 0; h < 2; h++) {
                int rg = r0g + h * 8;
                if (rg >= N_NODES) continue;
                float2* po = reinterpret_cast<float2*>(&out[(size_t)rg * 256 + colg]);
                float v0 = acc[mt][nt][h * 2], v1 = acc[mt][nt][h * 2 + 1];
                if (XPART) {
                    *po = make_float2(v0 + sBias[colg], v1 + sBias[colg + 1]);
                } else {
                    float2 old = *po;
                    *po = make_float2(old.x + v0, old.y + v1);
                }
            }
        }
    }
}

// ---------------- launch: fork-join DAG ----------------
extern "C" void kernel_launch(void* const* d_in, const int* in_sizes, int n_in,
                              void* d_out, int out_size) {
    const float* x  = (const float*)d_in[0];
    const int*   ei = (const int*)d_in[1];
    const float* Wl = (const float*)d_in[2];
    const float* Wr = (const float*)d_in[3];
    const float* br = (const float*)d_in[4];
    float* out = (float*)d_out;

    cudaFuncSetAttribute(gemm_part_kernel<true>,
                         cudaFuncAttributeMaxDynamicSharedMemorySize, GEMM_SMEM);
    cudaFuncSetAttribute(gemm_part_kernel<false>,
                         cudaFuncAttributeMaxDynamicSharedMemorySize, GEMM_SMEM);

    // fresh per call; kernel_launch runs once for correctness + once under
    // capture (replays never re-enter). Not destroyed: destroying a stream
    // mid-capture could invalidate the capture. Host objects only.
    cudaStream_t s1;
    cudaStreamCreateWithFlags(&s1, cudaStreamNonBlocking);
    cudaEvent_t eFork, eJoin;
    cudaEventCreateWithFlags(&eFork, cudaEventDisableTiming);
    cudaEventCreateWithFlags(&eJoin, cudaEventDisableTiming);

    dim3 ggrid((N_NODES + 127) / 128, 2);

    // fork side branch off the (captured) legacy stream
    cudaEventRecord(eFork, 0);
    cudaStreamWaitEvent(s1, eFork, 0);

    // side branch: x/W conversion + x-part GEMM (writes out = x-terms + bias)
    conv_x_kernel<<<N_NODES, 256, 0, s1>>>(x);
    conv_w_kernel<<<256, 256, 0, s1>>>(Wl, Wr);
    gemm_part_kernel<true><<<ggrid, GT, GEMM_SMEM, s1>>>(br, out);

    // main branch: CSR build + aggregation
    init_kernel<<<NB, 256>>>(ei);
    count_kernel<<<(N_EDGES + 255) / 256, 256>>>(ei);
    partsum_kernel<<<NB, 256>>>();
    scanwrite_kernel<<<NB, 256>>>();
    fill_kernel<<<(N_EDGES + 255) / 256, 256>>>(ei);
    aggregate_kernel<<<N_NODES, 256>>>(x);

    // join, then accumulate aggr-part GEMM into out
    cudaEventRecord(eJoin, s1);
    cudaStreamWaitEvent(0, eJoin, 0);
    gemm_part_kernel<false><<<ggrid, GT, GEMM_SMEM>>>(br, out);
}

// round 10
// speedup vs baseline: 1.1625x; 1.1625x over previous
#include <cuda_runtime.h>
#include <cuda_bf16.h>
#include <cstdint>

#define N_NODES 20000
#define N_EDGES 320000
#define D 256
#define NB 79          // ceil(20000/256) scan blocks

// ---------------- scratch (no allocations allowed) ----------------
// A' = [hi(x) | lo(x)] per row: 512 bf16 cols
__device__ __nv_bfloat16 g_Axl[(size_t)N_NODES * 512];
// W' rows 0-255 = Wl rows as [hi|lo]; rows 256-511 = Wr rows as [hi|lo]
__device__ __nv_bfloat16 g_Wyz[512 * 512];
// yz = [ y = x@Wl^T | z = x@Wr^T ] per row: 512 f32
__device__ float g_yz[(size_t)N_NODES * 512];
__device__ int g_count[N_NODES];
__device__ int g_off[N_NODES + 1];
__device__ int g_cursor[N_NODES];
__device__ int g_srclist[N_EDGES];
__device__ int g_bsum[NB];
__device__ int g_is64;

// ---------------- helpers ----------------
__device__ __forceinline__ uint32_t smem_u32(const void* p) {
    uint32_t a;
    asm("{ .reg .u64 t; cvta.to.shared.u64 t, %1; cvt.u32.u64 %0, t; }"
        : "=r"(a) : "l"(p));
    return a;
}
__device__ __forceinline__ void split_bf16(float v, __nv_bfloat16& hi, __nv_bfloat16& lo) {
    hi = __float2bfloat16(v);
    lo = __float2bfloat16(v - __bfloat162float(hi));
}
__device__ __forceinline__ void cp16(uint32_t dst, const void* src, int srcsz) {
    asm volatile("cp.async.cg.shared.global [%0], [%1], 16, %2;"
                 :: "r"(dst), "l"(src), "r"(srcsz));
}
__device__ __forceinline__ void cp_commit() { asm volatile("cp.async.commit_group;" ::: "memory"); }
__device__ __forceinline__ void cp_wait1()  { asm volatile("cp.async.wait_group 1;" ::: "memory"); }
__device__ __forceinline__ void cp_wait0()  { asm volatile("cp.async.wait_group 0;" ::: "memory"); }

__device__ __forceinline__ void ldm_x4(uint32_t* r, uint32_t addr) {
    asm volatile("ldmatrix.sync.aligned.m8n8.x4.shared.b16 {%0,%1,%2,%3}, [%4];"
                 : "=r"(r[0]), "=r"(r[1]), "=r"(r[2]), "=r"(r[3]) : "r"(addr));
}
__device__ __forceinline__ void mma16816(float* d, const uint32_t* a, const uint32_t* b) {
    asm volatile("mma.sync.aligned.m16n8k16.row.col.f32.bf16.bf16.f32 "
                 "{%0,%1,%2,%3}, {%4,%5,%6,%7}, {%8,%9}, {%0,%1,%2,%3};"
                 : "+f"(d[0]), "+f"(d[1]), "+f"(d[2]), "+f"(d[3])
                 : "r"(a[0]), "r"(a[1]), "r"(a[2]), "r"(a[3]), "r"(b[0]), "r"(b[1]));
}

// ---------------- init: zero counts + warp-parallel dtype sniff ----------------
// int64 little-endian with values < 2^31: every odd 32-bit word is 0.
__global__ void init_kernel(const int* __restrict__ ei) {
    int idx = blockIdx.x * 256 + threadIdx.x;
    if (idx < N_NODES) { g_count[idx] = 0; g_cursor[idx] = 0; }
    if (idx == 0) g_off[N_NODES] = N_EDGES;
    if (blockIdx.x == 0 && threadIdx.x < 32) {
        int nz = 0;
        for (int i = threadIdx.x; i < 512; i += 32)
            nz |= (ei[2 * i + 1] != 0);
        unsigned m = __ballot_sync(0xffffffffu, nz);
        if (threadIdx.x == 0) g_is64 = (m == 0);
    }
}

__global__ void count_kernel(const int* __restrict__ ei) {
    int e = blockIdx.x * blockDim.x + threadIdx.x;
    if (e < N_EDGES) {
        int dst = g_is64 ? ei[2 * (N_EDGES + e)] : ei[N_EDGES + e];
        atomicAdd(&g_count[dst], 1);
    }
}

// ---------------- hierarchical scan (proven R8 versions) ----------------
__global__ void partsum_kernel() {
    __shared__ int s[256];
    int tid = threadIdx.x;
    int idx = blockIdx.x * 256 + tid;
    s[tid] = (idx < N_NODES) ? g_count[idx] : 0;
    __syncthreads();
    for (int o = 128; o > 0; o >>= 1) {
        if (tid < o) s[tid] += s[tid + o];
        __syncthreads();
    }
    if (tid == 0) g_bsum[blockIdx.x] = s[0];
}

__global__ void scanwrite_kernel() {
    __shared__ int bs[128];
    __shared__ int sc[256];
    int tid = threadIdx.x;
    int b = blockIdx.x;
    if (tid < 128) bs[tid] = (tid < NB) ? g_bsum[tid] : 0;
    __syncthreads();
    for (int o = 1; o < 128; o <<= 1) {
        int v = (tid < 128 && tid >= o) ? bs[tid - o] : 0;
        __syncthreads();
        if (tid < 128) bs[tid] += v;
        __syncthreads();
    }
    int bp = (b == 0) ? 0 : bs[b - 1];
    int idx = b * 256 + tid;
    int cnt = (idx < N_NODES) ? g_count[idx] : 0;
    sc[tid] = cnt;
    __syncthreads();
    for (int o = 1; o < 256; o <<= 1) {
        int v = (tid >= o) ? sc[tid - o] : 0;
        __syncthreads();
        sc[tid] += v;
        __syncthreads();
    }
    if (idx < N_NODES) g_off[idx] = bp + sc[tid] - cnt;
}

__global__ void fill_kernel(const int* __restrict__ ei) {
    int e = blockIdx.x * blockDim.x + threadIdx.x;
    if (e >= N_EDGES) return;
    int src, dst;
    if (g_is64) { src = ei[2 * e]; dst = ei[2 * (N_EDGES + e)]; }
    else        { src = ei[e];     dst = ei[N_EDGES + e]; }
    int pos = atomicAdd(&g_cursor[dst], 1);
    g_srclist[g_off[dst] + pos] = src;
}

// ---------------- side-stream converters ----------------
__global__ void conv_x_kernel(const float* __restrict__ x) {
    int n = blockIdx.x;
    int c = threadIdx.x;
    float v = x[(size_t)n * D + c];
    __nv_bfloat16 hi, lo;
    split_bf16(v, hi, lo);
    g_Axl[(size_t)n * 512 + c] = hi;
    g_Axl[(size_t)n * 512 + 256 + c] = lo;
}

__global__ void conv_w_kernel(const float* __restrict__ Wl, const float* __restrict__ Wr) {
    int n = blockIdx.x;     // 0..255
    int c = threadIdx.x;    // 0..255
    __nv_bfloat16 hi, lo;
    split_bf16(Wl[n * D + c], hi, lo);
    g_Wyz[n * 512 + c] = hi;         g_Wyz[n * 512 + 256 + c] = lo;
    split_bf16(Wr[n * D + c], hi, lo);
    g_Wyz[(256 + n) * 512 + c] = hi; g_Wyz[(256 + n) * 512 + 256 + c] = lo;
}

// ---------------- mma.sync bf16 GEMM: yz = x @ [Wl|Wr]^T ----------------
// 3 terms (hi*hi, hi*lo, lo*hi) x 4 K-chunks of 64 = 12 chunks.
// CTA tile 128x128, 8 warps (2M x 4N), warp tile 64x32, m16n8k16 HMMA.
// Smem tiles [128 rows][64 bf16], 16B-chunk XOR swizzle (chunk ^ (row&7)).
#define GT 256
#define SM_A(b)   ((b) * 32768)
#define SM_B(b)   ((b) * 32768 + 16384)
#define GEMM_SMEM 65536

extern __shared__ char sm_dyn[];

__device__ __forceinline__ void stage_chunk(uint32_t sb, int b, int Acol, int Wcol, int kc,
                                            int row0, int col0, int tid) {
    uint32_t smA = sb + SM_A(b), smB = sb + SM_B(b);
    const char* Abase = (const char*)g_Axl;
    const char* Bbase = (const char*)g_Wyz;
#pragma unroll
    for (int it = 0; it < 4; it++) {
        int u = it * GT + tid;              // 0..1023
        int r  = u >> 3;                    // row 0..127
        int ck = u & 7;                     // 16B chunk 0..7
        uint32_t swo = (uint32_t)(r * 8 + (ck ^ (r & 7))) * 16;
        int grow = row0 + r;
        int ok = (grow < N_NODES);
        const char* asrc = Abase + ((size_t)(ok ? grow : 0) * 512 + Acol + kc + ck * 8) * 2;
        cp16(smA + swo, asrc, ok ? 16 : 0);
        const char* bsrc = Bbase + ((size_t)(col0 + r) * 512 + Wcol + kc + ck * 8) * 2;
        cp16(smB + swo, bsrc, 16);
    }
    cp_commit();
}

__global__ void __launch_bounds__(GT, 2)
gemm_yz_kernel() {
    uint32_t sb = smem_u32(sm_dyn);
    int tid  = threadIdx.x;
    int wid  = tid >> 5;
    int lane = tid & 31;
    int row0 = blockIdx.x * 128;
    int col0 = blockIdx.y * 128;         // 0..384 over 512 yz cols
    int m0w  = (wid & 1) * 64;
    int n0w  = (wid >> 1) * 32;

    float acc[4][4][4];
#pragma unroll
    for (int mt = 0; mt < 4; mt++)
#pragma unroll
        for (int nt = 0; nt < 4; nt++)
#pragma unroll
            for (int j = 0; j < 4; j++) acc[mt][nt][j] = 0.f;

    int a_m  = m0w + (lane & 15);
    int a_kh = (lane >> 4);
    int b_n  = n0w + (lane & 7) + ((lane >> 4) & 1) * 8;
    int b_kh = (lane >> 3) & 1;

    const int CH = 12;
#pragma unroll 1
    for (int c = 0; c <= CH; c++) {
        if (c < CH) {
            int p  = c >> 2;                 // term 0,1,2
            int kc = (c & 3) * 64;
            int Ac = (p == 2) ? 256 : 0;     // lo A only in term 2
            int Wc = (p == 1) ? 256 : 0;     // lo W only in term 1
            stage_chunk(sb, c & 1, Ac, Wc, kc, row0, col0, tid);
        }
        if (c == 0) continue;
        int b = (c - 1) & 1;
        if (c < CH) cp_wait1(); else cp_wait0();
        __syncthreads();

        uint32_t smA = sb + SM_A(b), smB = sb + SM_B(b);
#pragma unroll
        for (int ks = 0; ks < 4; ks++) {
            uint32_t afrag[4][4], bfrag[4][4];
            int ka = ks * 2 + a_kh;
            int kb = ks * 2 + b_kh;
#pragma unroll
            for (int mt = 0; mt < 4; mt++) {
                int m = a_m + mt * 16;
                ldm_x4(afrag[mt], smA + (uint32_t)(m * 8 + (ka ^ (m & 7))) * 16);
            }
#pragma unroll
            for (int np = 0; np < 2; np++) {
                int n = b_n + np * 16;
                uint32_t r4[4];
                ldm_x4(r4, smB + (uint32_t)(n * 8 + (kb ^ (n & 7))) * 16);
                bfrag[np * 2][0]     = r4[0]; bfrag[np * 2][1]     = r4[1];
                bfrag[np * 2 + 1][0] = r4[2]; bfrag[np * 2 + 1][1] = r4[3];
            }
#pragma unroll
            for (int mt = 0; mt < 4; mt++)
#pragma unroll
                for (int nt = 0; nt < 4; nt++)
                    mma16816(acc[mt][nt], afrag[mt], bfrag[nt]);
        }
        __syncthreads();
    }

    int cr = lane >> 2;
    int cc = (lane & 3) * 2;
#pragma unroll
    for (int mt = 0; mt < 4; mt++) {
        int r0g = row0 + m0w + mt * 16 + cr;
#pragma unroll
        for (int nt = 0; nt < 4; nt++) {
            int colg = col0 + n0w + nt * 8 + cc;
#pragma unroll
            for (int h = 0; h < 2; h++) {
                int rg = r0g + h * 8;
                if (rg < N_NODES)
                    *reinterpret_cast<float2*>(&g_yz[(size_t)rg * 512 + colg]) =
                        make_float2(acc[mt][nt][h * 2], acc[mt][nt][h * 2 + 1]);
            }
        }
    }
}

// ---------------- final: out = segmean(y) + z + bias ----------------
// segmean commutes with the linear map, so gather in y-space.
#define AGG_TILE 64
__global__ void aggregate_final_kernel(const float* __restrict__ br,
                                       float* __restrict__ out) {
    int n = blockIdx.x;
    int c = threadIdx.x;
    __shared__ int ssrc[AGG_TILE];

    float z = g_yz[(size_t)n * 512 + 256 + c];
    float bias = __ldg(&br[c]);

    int off0 = g_off[n];
    int off1 = g_off[n + 1];
    float sum = 0.f;
    for (int base = off0; base < off1; base += AGG_TILE) {
        int cnt = min(AGG_TILE, off1 - base);
        __syncthreads();
        if (c < cnt) ssrc[c] = g_srclist[base + c];
        __syncthreads();
#pragma unroll 8
        for (int i = 0; i < cnt; i++)
            sum += __ldg(&g_yz[(size_t)ssrc[i] * 512 + c]);
    }
    float m = sum * (1.0f / fmaxf((float)(off1 - off0), 1.0f));
    out[(size_t)n * 256 + c] = m + z + bias;
}

// ---------------- launch: fork-join DAG ----------------
extern "C" void kernel_launch(void* const* d_in, const int* in_sizes, int n_in,
                              void* d_out, int out_size) {
    const float* x  = (const float*)d_in[0];
    const int*   ei = (const int*)d_in[1];
    const float* Wl = (const float*)d_in[2];
    const float* Wr = (const float*)d_in[3];
    const float* br = (const float*)d_in[4];
    float* out = (float*)d_out;

    cudaFuncSetAttribute(gemm_yz_kernel,
                         cudaFuncAttributeMaxDynamicSharedMemorySize, GEMM_SMEM);

    // fresh per call; capture runs kernel_launch once, replays never re-enter.
    cudaStream_t s1;
    cudaStreamCreateWithFlags(&s1, cudaStreamNonBlocking);
    cudaEvent_t eFork, eJoin;
    cudaEventCreateWithFlags(&eFork, cudaEventDisableTiming);
    cudaEventCreateWithFlags(&eJoin, cudaEventDisableTiming);

    // fork side branch off the (captured) legacy stream
    cudaEventRecord(eFork, 0);
    cudaStreamWaitEvent(s1, eFork, 0);

    // side branch: x/W conversion + full GEMM into yz scratch (no CSR dep)
    conv_x_kernel<<<N_NODES, 256, 0, s1>>>(x);
    conv_w_kernel<<<256, 256, 0, s1>>>(Wl, Wr);
    gemm_yz_kernel<<<dim3((N_NODES + 127) / 128, 4), GT, GEMM_SMEM, s1>>>();

    // main branch: CSR build (atomic-bound; complementary to GEMM)
    init_kernel<<<NB, 256>>>(ei);
    count_kernel<<<(N_EDGES + 255) / 256, 256>>>(ei);
    partsum_kernel<<<NB, 256>>>();
    scanwrite_kernel<<<NB, 256>>>();
    fill_kernel<<<(N_EDGES + 255) / 256, 256>>>(ei);

    // join, then final fused gather+add
    cudaEventRecord(eJoin, s1);
    cudaStreamWaitEvent(0, eJoin, 0);
    aggregate_final_kernel<<<N_NODES, 256>>>(br, out);
}

// round 12
// speedup vs baseline: 1.1824x; 1.0171x over previous
#include <cuda_runtime.h>
#include <cuda_bf16.h>
#include <cuda_fp16.h>
#include <cstdint>

#define N_NODES 20000
#define N_EDGES 320000
#define D 256
#define NB 79          // ceil(20000/256) scan blocks

// ---------------- scratch (no allocations allowed) ----------------
// A' = [hi(x) | lo(x)] per row: 512 bf16 cols
__device__ __nv_bfloat16 g_Axl[(size_t)N_NODES * 512];
// W' rows 0-255 = Wl rows as [hi|lo]; rows 256-511 = Wr rows as [hi|lo]
__device__ __nv_bfloat16 g_Wyz[512 * 512];
// y = x@Wl^T as fp16 (gathered 16x per edge -> half traffic), z = x@Wr^T as f32
__device__ __half g_yh[(size_t)N_NODES * 256];
__device__ float  g_z[(size_t)N_NODES * 256];
__device__ int g_count[N_NODES];
__device__ int g_off[N_NODES + 1];
__device__ int g_cursor[N_NODES];    // pre-seeded with offsets by scanwrite
__device__ int g_srclist[N_EDGES];
__device__ int g_bsum[NB];

// ---------------- helpers ----------------
__device__ __forceinline__ uint32_t smem_u32(const void* p) {
    uint32_t a;
    asm("{ .reg .u64 t; cvta.to.shared.u64 t, %1; cvt.u32.u64 %0, t; }"
        : "=r"(a) : "l"(p));
    return a;
}
__device__ __forceinline__ void split_bf16(float v, __nv_bfloat16& hi, __nv_bfloat16& lo) {
    hi = __float2bfloat16(v);
    lo = __float2bfloat16(v - __bfloat162float(hi));
}
__device__ __forceinline__ void cp16(uint32_t dst, const void* src, int srcsz) {
    asm volatile("cp.async.cg.shared.global [%0], [%1], 16, %2;"
                 :: "r"(dst), "l"(src), "r"(srcsz));
}
__device__ __forceinline__ void cp_commit() { asm volatile("cp.async.commit_group;" ::: "memory"); }
__device__ __forceinline__ void cp_wait1()  { asm volatile("cp.async.wait_group 1;" ::: "memory"); }
__device__ __forceinline__ void cp_wait0()  { asm volatile("cp.async.wait_group 0;" ::: "memory"); }

__device__ __forceinline__ void ldm_x4(uint32_t* r, uint32_t addr) {
    asm volatile("ldmatrix.sync.aligned.m8n8.x4.shared.b16 {%0,%1,%2,%3}, [%4];"
                 : "=r"(r[0]), "=r"(r[1]), "=r"(r[2]), "=r"(r[3]) : "r"(addr));
}
__device__ __forceinline__ void mma16816(float* d, const uint32_t* a, const uint32_t* b) {
    asm volatile("mma.sync.aligned.m16n8k16.row.col.f32.bf16.bf16.f32 "
                 "{%0,%1,%2,%3}, {%4,%5,%6,%7}, {%8,%9}, {%0,%1,%2,%3};"
                 : "+f"(d[0]), "+f"(d[1]), "+f"(d[2]), "+f"(d[3])
                 : "r"(a[0]), "r"(a[1]), "r"(a[2]), "r"(a[3]), "r"(b[0]), "r"(b[1]));
}

// per-block dtype sniff: int64-LE with values < 2^31 => first 64 odd words all 0.
// int32 data: those words are random edge indices, P(all 64 zero) ~ (5e-5)^64 = 0.
__device__ __forceinline__ int block_is64(const int* __restrict__ ei, int* s_nz) {
    int tid = threadIdx.x;
    if (tid == 0) *s_nz = 0;
    __syncthreads();
    if (tid < 64 && ei[2 * tid + 1] != 0) atomicOr(s_nz, 1);
    __syncthreads();
    return (*s_nz == 0);
}

// ---------------- CSR build ----------------
__global__ void zero_kernel() {
    int i = blockIdx.x * 1024 + threadIdx.x;
    // 20 blocks x 1024 threads, 1 int each covers 20480 >= N_NODES
    if (i < N_NODES) g_count[i] = 0;
}

__global__ void count_kernel(const int* __restrict__ ei) {
    __shared__ int s_nz;
    int is64 = block_is64(ei, &s_nz);
    int e = blockIdx.x * blockDim.x + threadIdx.x;
    if (e < N_EDGES) {
        int dst = is64 ? ei[2 * (N_EDGES + e)] : ei[N_EDGES + e];
        atomicAdd(&g_count[dst], 1);
    }
}

__global__ void partsum_kernel() {
    __shared__ int s[256];
    int tid = threadIdx.x;
    int idx = blockIdx.x * 256 + tid;
    s[tid] = (idx < N_NODES) ? g_count[idx] : 0;
    __syncthreads();
    for (int o = 128; o > 0; o >>= 1) {
        if (tid < o) s[tid] += s[tid + o];
        __syncthreads();
    }
    if (tid == 0) g_bsum[blockIdx.x] = s[0];
}

__global__ void scanwrite_kernel() {
    __shared__ int bs[128];
    __shared__ int sc[256];
    int tid = threadIdx.x;
    int b = blockIdx.x;
    if (tid < 128) bs[tid] = (tid < NB) ? g_bsum[tid] : 0;
    __syncthreads();
    for (int o = 1; o < 128; o <<= 1) {
        int v = (tid < 128 && tid >= o) ? bs[tid - o] : 0;
        __syncthreads();
        if (tid < 128) bs[tid] += v;
        __syncthreads();
    }
    int bp = (b == 0) ? 0 : bs[b - 1];
    int idx = b * 256 + tid;
    int cnt = (idx < N_NODES) ? g_count[idx] : 0;
    sc[tid] = cnt;
    __syncthreads();
    for (int o = 1; o < 256; o <<= 1) {
        int v = (tid >= o) ? sc[tid - o] : 0;
        __syncthreads();
        sc[tid] += v;
        __syncthreads();
    }
    if (idx < N_NODES) {
        int off = bp + sc[tid] - cnt;
        g_off[idx] = off;
        g_cursor[idx] = off;           // absolute slot counters for fill
    }
    if (b == 0 && tid == 0) g_off[N_NODES] = N_EDGES;
}

__global__ void fill_kernel(const int* __restrict__ ei) {
    __shared__ int s_nz;
    int is64 = block_is64(ei, &s_nz);
    int e = blockIdx.x * blockDim.x + threadIdx.x;
    if (e >= N_EDGES) return;
    int src, dst;
    if (is64) { src = ei[2 * e]; dst = ei[2 * (N_EDGES + e)]; }
    else      { src = ei[e];     dst = ei[N_EDGES + e]; }
    int slot = atomicAdd(&g_cursor[dst], 1);   // already absolute
    g_srclist[slot] = src;
}

// ---------------- side-stream converters (4B packed stores) ----------------
__global__ void conv_x_kernel(const float* __restrict__ x) {
    int n = blockIdx.x;
    int c2 = threadIdx.x;                  // 128 threads, 2 cols each
    float2 v = *reinterpret_cast<const float2*>(&x[(size_t)n * D + c2 * 2]);
    __nv_bfloat16 h0, l0, h1, l1;
    split_bf16(v.x, h0, l0);
    split_bf16(v.y, h1, l1);
    __nv_bfloat162* base = reinterpret_cast<__nv_bfloat162*>(&g_Axl[(size_t)n * 512]);
    base[c2]       = __nv_bfloat162(h0, h1);
    base[128 + c2] = __nv_bfloat162(l0, l1);
}

__global__ void conv_w_kernel(const float* __restrict__ Wl, const float* __restrict__ Wr) {
    int n = blockIdx.x;                    // 0..255
    int c2 = threadIdx.x;                  // 128 threads, 2 cols each
    float2 a = *reinterpret_cast<const float2*>(&Wl[n * D + c2 * 2]);
    float2 b = *reinterpret_cast<const float2*>(&Wr[n * D + c2 * 2]);
    __nv_bfloat16 h0, l0, h1, l1;
    __nv_bfloat162* rl = reinterpret_cast<__nv_bfloat162*>(&g_Wyz[n * 512]);
    __nv_bfloat162* rr = reinterpret_cast<__nv_bfloat162*>(&g_Wyz[(256 + n) * 512]);
    split_bf16(a.x, h0, l0); split_bf16(a.y, h1, l1);
    rl[c2] = __nv_bfloat162(h0, h1); rl[128 + c2] = __nv_bfloat162(l0, l1);
    split_bf16(b.x, h0, l0); split_bf16(b.y, h1, l1);
    rr[c2] = __nv_bfloat162(h0, h1); rr[128 + c2] = __nv_bfloat162(l0, l1);
}

// ---------------- mma.sync bf16 GEMM: [y|z] = x @ [Wl|Wr]^T ----------------
// 3 terms (hi*hi, hi*lo, lo*hi) x 4 K-chunks of 64 = 12 chunks.
// CTA tile 128x128, 8 warps (2M x 4N), warp tile 64x32, m16n8k16 HMMA.
#define GT 256
#define SM_A(b)   ((b) * 32768)
#define SM_B(b)   ((b) * 32768 + 16384)
#define GEMM_SMEM 65536

extern __shared__ char sm_dyn[];

__device__ __forceinline__ void stage_chunk(uint32_t sb, int b, int Acol, int Wcol, int kc,
                                            int row0, int col0, int tid) {
    uint32_t smA = sb + SM_A(b), smB = sb + SM_B(b);
    const char* Abase = (const char*)g_Axl;
    const char* Bbase = (const char*)g_Wyz;
#pragma unroll
    for (int it = 0; it < 4; it++) {
        int u = it * GT + tid;              // 0..1023
        int r  = u >> 3;                    // row 0..127
        int ck = u & 7;                     // 16B chunk 0..7
        uint32_t swo = (uint32_t)(r * 8 + (ck ^ (r & 7))) * 16;
        int grow = row0 + r;
        int ok = (grow < N_NODES);
        const char* asrc = Abase + ((size_t)(ok ? grow : 0) * 512 + Acol + kc + ck * 8) * 2;
        cp16(smA + swo, asrc, ok ? 16 : 0);
        const char* bsrc = Bbase + ((size_t)(col0 + r) * 512 + Wcol + kc + ck * 8) * 2;
        cp16(smB + swo, bsrc, 16);
    }
    cp_commit();
}

__global__ void __launch_bounds__(GT, 2)
gemm_yz_kernel() {
    uint32_t sb = smem_u32(sm_dyn);
    int tid  = threadIdx.x;
    int wid  = tid >> 5;
    int lane = tid & 31;
    int row0 = blockIdx.x * 128;
    int col0 = blockIdx.y * 128;         // by 0,1 -> y cols; 2,3 -> z cols
    int m0w  = (wid & 1) * 64;
    int n0w  = (wid >> 1) * 32;

    float acc[4][4][4];
#pragma unroll
    for (int mt = 0; mt < 4; mt++)
#pragma unroll
        for (int nt = 0; nt < 4; nt++)
#pragma unroll
            for (int j = 0; j < 4; j++) acc[mt][nt][j] = 0.f;

    int a_m  = m0w + (lane & 15);
    int a_kh = (lane >> 4);
    int b_n  = n0w + (lane & 7) + ((lane >> 4) & 1) * 8;
    int b_kh = (lane >> 3) & 1;

    const int CH = 12;
#pragma unroll 1
    for (int c = 0; c <= CH; c++) {
        if (c < CH) {
            int p  = c >> 2;                 // term 0,1,2
            int kc = (c & 3) * 64;
            int Ac = (p == 2) ? 256 : 0;     // lo A only in term 2
            int Wc = (p == 1) ? 256 : 0;     // lo W only in term 1
            stage_chunk(sb, c & 1, Ac, Wc, kc, row0, col0, tid);
        }
        if (c == 0) continue;
        int b = (c - 1) & 1;
        if (c < CH) cp_wait1(); else cp_wait0();
        __syncthreads();

        uint32_t smA = sb + SM_A(b), smB = sb + SM_B(b);
#pragma unroll
        for (int ks = 0; ks < 4; ks++) {
            uint32_t afrag[4][4], bfrag[4][4];
            int ka = ks * 2 + a_kh;
            int kb = ks * 2 + b_kh;
#pragma unroll
            for (int mt = 0; mt < 4; mt++) {
                int m = a_m + mt * 16;
                ldm_x4(afrag[mt], smA + (uint32_t)(m * 8 + (ka ^ (m & 7))) * 16);
            }
#pragma unroll
            for (int np = 0; np < 2; np++) {
                int n = b_n + np * 16;
                uint32_t r4[4];
                ldm_x4(r4, smB + (uint32_t)(n * 8 + (kb ^ (n & 7))) * 16);
                bfrag[np * 2][0]     = r4[0]; bfrag[np * 2][1]     = r4[1];
                bfrag[np * 2 + 1][0] = r4[2]; bfrag[np * 2 + 1][1] = r4[3];
            }
#pragma unroll
            for (int mt = 0; mt < 4; mt++)
#pragma unroll
                for (int nt = 0; nt < 4; nt++)
                    mma16816(acc[mt][nt], afrag[mt], bfrag[nt]);
        }
        __syncthreads();
    }

    // epilogue: y cols -> fp16 g_yh, z cols -> f32 g_z
    int cr = lane >> 2;
    int cc = (lane & 3) * 2;
    bool is_y = (col0 < 256);
#pragma unroll
    for (int mt = 0; mt < 4; mt++) {
        int r0g = row0 + m0w + mt * 16 + cr;
#pragma unroll
        for (int nt = 0; nt < 4; nt++) {
            int colg = col0 + n0w + nt * 8 + cc;
#pragma unroll
            for (int h = 0; h < 2; h++) {
                int rg = r0g + h * 8;
                if (rg >= N_NODES) continue;
                float v0 = acc[mt][nt][h * 2], v1 = acc[mt][nt][h * 2 + 1];
                if (is_y) {
                    *reinterpret_cast<__half2*>(&g_yh[(size_t)rg * 256 + colg]) =
                        __floats2half2_rn(v0, v1);
                } else {
                    *reinterpret_cast<float2*>(&g_z[(size_t)rg * 256 + (colg - 256)]) =
                        make_float2(v0, v1);
                }
            }
        }
    }
}

// ---------------- final: out = segmean(y) + z + bias (fp16 gather) ----------------
#define AGG_TILE 64
__global__ void aggregate_final_kernel(const float* __restrict__ br,
                                       float* __restrict__ out) {
    int n = blockIdx.x;
    int c = threadIdx.x;
    __shared__ int ssrc[AGG_TILE];

    float z = g_z[(size_t)n * 256 + c];
    float bias = __ldg(&br[c]);

    int off0 = g_off[n];
    int off1 = g_off[n + 1];
    float sum = 0.f;
    for (int base = off0; base < off1; base += AGG_TILE) {
        int cnt = min(AGG_TILE, off1 - base);
        __syncthreads();
        if (c < cnt) ssrc[c] = g_srclist[base + c];
        __syncthreads();
#pragma unroll 8
        for (int i = 0; i < cnt; i++)
            sum += __half2float(__ldg(&g_yh[(size_t)ssrc[i] * 256 + c]));
    }
    float m = sum * (1.0f / fmaxf((float)(off1 - off0), 1.0f));
    out[(size_t)n * 256 + c] = m + z + bias;
}

// ---------------- launch: fork-join DAG ----------------
extern "C" void kernel_launch(void* const* d_in, const int* in_sizes, int n_in,
                              void* d_out, int out_size) {
    const float* x  = (const float*)d_in[0];
    const int*   ei = (const int*)d_in[1];
    const float* Wl = (const float*)d_in[2];
    const float* Wr = (const float*)d_in[3];
    const float* br = (const float*)d_in[4];
    float* out = (float*)d_out;

    cudaFuncSetAttribute(gemm_yz_kernel,
                         cudaFuncAttributeMaxDynamicSharedMemorySize, GEMM_SMEM);

    // fresh per call; capture runs kernel_launch once, replays never re-enter.
    cudaStream_t s1;
    cudaStreamCreateWithFlags(&s1, cudaStreamNonBlocking);
    cudaEvent_t eFork, eJoin;
    cudaEventCreateWithFlags(&eFork, cudaEventDisableTiming);
    cudaEventCreateWithFlags(&eJoin, cudaEventDisableTiming);

    // fork side branch off the (captured) legacy stream
    cudaEventRecord(eFork, 0);
    cudaStreamWaitEvent(s1, eFork, 0);

    // side branch: W/x conversion + full GEMM into y(fp16)/z(f32) (no CSR dep)
    conv_w_kernel<<<256, 128, 0, s1>>>(Wl, Wr);
    conv_x_kernel<<<N_NODES, 128, 0, s1>>>(x);
    gemm_yz_kernel<<<dim3((N_NODES + 127) / 128, 4), GT, GEMM_SMEM, s1>>>();

    // main branch: CSR build (atomic-bound; complementary to GEMM)
    zero_kernel<<<20, 1024>>>();
    count_kernel<<<(N_EDGES + 255) / 256, 256>>>(ei);
    partsum_kernel<<<NB, 256>>>();
    scanwrite_kernel<<<NB, 256>>>();
    fill_kernel<<<(N_EDGES + 255) / 256, 256>>>(ei);

    // join, then final fused gather+add
    cudaEventRecord(eJoin, s1);
    cudaStreamWaitEvent(0, eJoin, 0);
    aggregate_final_kernel<<<N_NODES, 256>>>(br, out);
}

// round 13
// speedup vs baseline: 1.4095x; 1.1920x over previous
#include <cuda_runtime.h>
#include <cuda_bf16.h>
#include <cuda_fp16.h>
#include <cstdint>

#define N_NODES 20000
#define N_EDGES 320000
#define D 256
#define NB 79          // ceil(20000/256) scan blocks

// ---------------- scratch (no allocations allowed) ----------------
// A' = [hi(x) | lo(x)] per row: 512 bf16 cols
__device__ __nv_bfloat16 g_Axl[(size_t)N_NODES * 512];
// W' rows 0-255 = Wl rows as [hi|lo]; rows 256-511 = Wr rows as [hi|lo]
__device__ __nv_bfloat16 g_Wyz[512 * 512];
// y = x@Wl^T as fp16 (gather traffic halved), z = x@Wr^T as f32
__device__ __half g_yh[(size_t)N_NODES * 256];
__device__ float  g_z[(size_t)N_NODES * 256];
__device__ int g_count[N_NODES];
__device__ int g_off[N_NODES + 1];
__device__ int g_cursor[N_NODES];    // pre-seeded with offsets by scanwrite
__device__ int g_srclist[N_EDGES];
__device__ int g_bsum[NB];

// ---------------- helpers ----------------
__device__ __forceinline__ uint32_t smem_u32(const void* p) {
    uint32_t a;
    asm("{ .reg .u64 t; cvta.to.shared.u64 t, %1; cvt.u32.u64 %0, t; }"
        : "=r"(a) : "l"(p));
    return a;
}
__device__ __forceinline__ void split_bf16(float v, __nv_bfloat16& hi, __nv_bfloat16& lo) {
    hi = __float2bfloat16(v);
    lo = __float2bfloat16(v - __bfloat162float(hi));
}
__device__ __forceinline__ void cp16(uint32_t dst, const void* src, int srcsz) {
    asm volatile("cp.async.cg.shared.global [%0], [%1], 16, %2;"
                 :: "r"(dst), "l"(src), "r"(srcsz));
}
__device__ __forceinline__ void cp_commit() { asm volatile("cp.async.commit_group;" ::: "memory"); }
__device__ __forceinline__ void cp_wait1()  { asm volatile("cp.async.wait_group 1;" ::: "memory"); }
__device__ __forceinline__ void cp_wait0()  { asm volatile("cp.async.wait_group 0;" ::: "memory"); }

__device__ __forceinline__ void ldm_x4(uint32_t* r, uint32_t addr) {
    asm volatile("ldmatrix.sync.aligned.m8n8.x4.shared.b16 {%0,%1,%2,%3}, [%4];"
                 : "=r"(r[0]), "=r"(r[1]), "=r"(r[2]), "=r"(r[3]) : "r"(addr));
}
__device__ __forceinline__ void mma16816(float* d, const uint32_t* a, const uint32_t* b) {
    asm volatile("mma.sync.aligned.m16n8k16.row.col.f32.bf16.bf16.f32 "
                 "{%0,%1,%2,%3}, {%4,%5,%6,%7}, {%8,%9}, {%0,%1,%2,%3};"
                 : "+f"(d[0]), "+f"(d[1]), "+f"(d[2]), "+f"(d[3])
                 : "r"(a[0]), "r"(a[1]), "r"(a[2]), "r"(a[3]), "r"(b[0]), "r"(b[1]));
}

// per-block dtype sniff: int64-LE with values < 2^31 => first 64 odd words all 0.
__device__ __forceinline__ int block_is64(const int* __restrict__ ei, int* s_nz) {
    int tid = threadIdx.x;
    if (tid == 0) *s_nz = 0;
    __syncthreads();
    if (tid < 64 && ei[2 * tid + 1] != 0) atomicOr(s_nz, 1);
    __syncthreads();
    return (*s_nz == 0);
}

// ---------------- CSR build ----------------
__global__ void zero_kernel() {
    int i = blockIdx.x * 1024 + threadIdx.x;
    if (i < N_NODES) g_count[i] = 0;
}

__global__ void count_kernel(const int* __restrict__ ei) {
    __shared__ int s_nz;
    int is64 = block_is64(ei, &s_nz);
    int e = blockIdx.x * blockDim.x + threadIdx.x;
    if (e < N_EDGES) {
        int dst = is64 ? ei[2 * (N_EDGES + e)] : ei[N_EDGES + e];
        atomicAdd(&g_count[dst], 1);
    }
}

__global__ void partsum_kernel() {
    __shared__ int s[256];
    int tid = threadIdx.x;
    int idx = blockIdx.x * 256 + tid;
    s[tid] = (idx < N_NODES) ? g_count[idx] : 0;
    __syncthreads();
    for (int o = 128; o > 0; o >>= 1) {
        if (tid < o) s[tid] += s[tid + o];
        __syncthreads();
    }
    if (tid == 0) g_bsum[blockIdx.x] = s[0];
}

__global__ void scanwrite_kernel() {
    __shared__ int bs[128];
    __shared__ int sc[256];
    int tid = threadIdx.x;
    int b = blockIdx.x;
    if (tid < 128) bs[tid] = (tid < NB) ? g_bsum[tid] : 0;
    __syncthreads();
    for (int o = 1; o < 128; o <<= 1) {
        int v = (tid < 128 && tid >= o) ? bs[tid - o] : 0;
        __syncthreads();
        if (tid < 128) bs[tid] += v;
        __syncthreads();
    }
    int bp = (b == 0) ? 0 : bs[b - 1];
    int idx = b * 256 + tid;
    int cnt = (idx < N_NODES) ? g_count[idx] : 0;
    sc[tid] = cnt;
    __syncthreads();
    for (int o = 1; o < 256; o <<= 1) {
        int v = (tid >= o) ? sc[tid - o] : 0;
        __syncthreads();
        sc[tid] += v;
        __syncthreads();
    }
    if (idx < N_NODES) {
        int off = bp + sc[tid] - cnt;
        g_off[idx] = off;
        g_cursor[idx] = off;           // absolute slot counters for fill
    }
    if (b == 0 && tid == 0) g_off[N_NODES] = N_EDGES;
}

__global__ void fill_kernel(const int* __restrict__ ei) {
    __shared__ int s_nz;
    int is64 = block_is64(ei, &s_nz);
    int e = blockIdx.x * blockDim.x + threadIdx.x;
    if (e >= N_EDGES) return;
    int src, dst;
    if (is64) { src = ei[2 * e]; dst = ei[2 * (N_EDGES + e)]; }
    else      { src = ei[e];     dst = ei[N_EDGES + e]; }
    int slot = atomicAdd(&g_cursor[dst], 1);   // already absolute
    g_srclist[slot] = src;
}

// ---------------- converters ----------------
// 256 threads = 4 rows/block, float4 loads, 8B packed bf16 stores
__global__ void conv_x_kernel(const float* __restrict__ x) {
    int n  = blockIdx.x * 4 + (threadIdx.x >> 6);
    int c4 = (threadIdx.x & 63) * 4;
    float4 v = *reinterpret_cast<const float4*>(&x[(size_t)n * D + c4]);
    __nv_bfloat16 h[4], l[4];
    split_bf16(v.x, h[0], l[0]); split_bf16(v.y, h[1], l[1]);
    split_bf16(v.z, h[2], l[2]); split_bf16(v.w, h[3], l[3]);
    uint32_t hp0, hp1, lp0, lp1;
    memcpy(&hp0, &h[0], 4); memcpy(&hp1, &h[2], 4);
    memcpy(&lp0, &l[0], 4); memcpy(&lp1, &l[2], 4);
    uint2* basehi = reinterpret_cast<uint2*>(&g_Axl[(size_t)n * 512 + c4]);
    uint2* baselo = reinterpret_cast<uint2*>(&g_Axl[(size_t)n * 512 + 256 + c4]);
    *basehi = make_uint2(hp0, hp1);
    *baselo = make_uint2(lp0, lp1);
}

__global__ void conv_w_kernel(const float* __restrict__ Wl, const float* __restrict__ Wr) {
    int n = blockIdx.x;                    // 0..255
    int c2 = threadIdx.x;                  // 128 threads, 2 cols each
    float2 a = *reinterpret_cast<const float2*>(&Wl[n * D + c2 * 2]);
    float2 b = *reinterpret_cast<const float2*>(&Wr[n * D + c2 * 2]);
    __nv_bfloat16 h0, l0, h1, l1;
    __nv_bfloat162* rl = reinterpret_cast<__nv_bfloat162*>(&g_Wyz[n * 512]);
    __nv_bfloat162* rr = reinterpret_cast<__nv_bfloat162*>(&g_Wyz[(256 + n) * 512]);
    split_bf16(a.x, h0, l0); split_bf16(a.y, h1, l1);
    rl[c2] = __nv_bfloat162(h0, h1); rl[128 + c2] = __nv_bfloat162(l0, l1);
    split_bf16(b.x, h0, l0); split_bf16(b.y, h1, l1);
    rr[c2] = __nv_bfloat162(h0, h1); rr[128 + c2] = __nv_bfloat162(l0, l1);
}

// ---------------- mma.sync bf16 GEMM: [y|z] = x @ [Wl|Wr]^T ----------------
// 3 terms (hi*hi, hi*lo, lo*hi) x 4 K-chunks of 64 = 12 chunks.
// CTA tile 128x64 (finer grid: 157x8 = 1256 CTAs @ 3/SM = 444 slots -> 2.83 waves,
// vs 128x128's effective 3-wave quantization). 8 warps 4Mx2N, warp tile 32x32.
#define GT 256
#define SM_A(b)   ((b) * 24576)
#define SM_B(b)   ((b) * 24576 + 16384)
#define GEMM_SMEM 49152

extern __shared__ char sm_dyn[];

__device__ __forceinline__ void stage_chunk(uint32_t sb, int b, int Acol, int Wcol, int kc,
                                            int row0, int col0, int tid) {
    uint32_t smA = sb + SM_A(b), smB = sb + SM_B(b);
    const char* Abase = (const char*)g_Axl;
    const char* Bbase = (const char*)g_Wyz;
    // A: 128 rows x 8 chunks = 1024 units
#pragma unroll
    for (int it = 0; it < 4; it++) {
        int u = it * GT + tid;
        int r  = u >> 3;
        int ck = u & 7;
        uint32_t swo = (uint32_t)(r * 8 + (ck ^ (r & 7))) * 16;
        int grow = row0 + r;
        int ok = (grow < N_NODES);
        const char* asrc = Abase + ((size_t)(ok ? grow : 0) * 512 + Acol + kc + ck * 8) * 2;
        cp16(smA + swo, asrc, ok ? 16 : 0);
    }
    // B: 64 rows x 8 chunks = 512 units
#pragma unroll
    for (int it = 0; it < 2; it++) {
        int u = it * GT + tid;
        int r  = u >> 3;                    // 0..63
        int ck = u & 7;
        uint32_t swo = (uint32_t)(r * 8 + (ck ^ (r & 7))) * 16;
        const char* bsrc = Bbase + ((size_t)(col0 + r) * 512 + Wcol + kc + ck * 8) * 2;
        cp16(smB + swo, bsrc, 16);
    }
    cp_commit();
}

__global__ void __launch_bounds__(GT, 3)
gemm_yz_kernel() {
    uint32_t sb = smem_u32(sm_dyn);
    int tid  = threadIdx.x;
    int wid  = tid >> 5;
    int lane = tid & 31;
    int row0 = blockIdx.x * 128;
    int col0 = blockIdx.y * 64;          // 0..448 over 512 yz cols
    int m0w  = (wid & 3) * 32;           // 4 warps along M
    int n0w  = (wid >> 2) * 32;          // 2 warps along N

    float acc[2][4][4];
#pragma unroll
    for (int mt = 0; mt < 2; mt++)
#pragma unroll
        for (int nt = 0; nt < 4; nt++)
#pragma unroll
            for (int j = 0; j < 4; j++) acc[mt][nt][j] = 0.f;

    int a_m  = m0w + (lane & 15);
    int a_kh = (lane >> 4);
    int b_n  = n0w + (lane & 7) + ((lane >> 4) & 1) * 8;
    int b_kh = (lane >> 3) & 1;

    const int CH = 12;
#pragma unroll 1
    for (int c = 0; c <= CH; c++) {
        if (c < CH) {
            int p  = c >> 2;                 // term 0,1,2
            int kc = (c & 3) * 64;
            int Ac = (p == 2) ? 256 : 0;     // lo A only in term 2
            int Wc = (p == 1) ? 256 : 0;     // lo W only in term 1
            stage_chunk(sb, c & 1, Ac, Wc, kc, row0, col0, tid);
        }
        if (c == 0) continue;
        int b = (c - 1) & 1;
        if (c < CH) cp_wait1(); else cp_wait0();
        __syncthreads();

        uint32_t smA = sb + SM_A(b), smB = sb + SM_B(b);
#pragma unroll
        for (int ks = 0; ks < 4; ks++) {
            uint32_t afrag[2][4], bfrag[4][4];
            int ka = ks * 2 + a_kh;
            int kb = ks * 2 + b_kh;
#pragma unroll
            for (int mt = 0; mt < 2; mt++) {
                int m = a_m + mt * 16;
                ldm_x4(afrag[mt], smA + (uint32_t)(m * 8 + (ka ^ (m & 7))) * 16);
            }
#pragma unroll
            for (int np = 0; np < 2; np++) {
                int n = b_n + np * 16;
                uint32_t r4[4];
                ldm_x4(r4, smB + (uint32_t)(n * 8 + (kb ^ (n & 7))) * 16);
                bfrag[np * 2][0]     = r4[0]; bfrag[np * 2][1]     = r4[1];
                bfrag[np * 2 + 1][0] = r4[2]; bfrag[np * 2 + 1][1] = r4[3];
            }
#pragma unroll
            for (int mt = 0; mt < 2; mt++)
#pragma unroll
                for (int nt = 0; nt < 4; nt++)
                    mma16816(acc[mt][nt], afrag[mt], bfrag[nt]);
        }
        __syncthreads();
    }

    // epilogue: y cols -> fp16 g_yh, z cols -> f32 g_z
    int cr = lane >> 2;
    int cc = (lane & 3) * 2;
    bool is_y = (col0 < 256);
#pragma unroll
    for (int mt = 0; mt < 2; mt++) {
        int r0g = row0 + m0w + mt * 16 + cr;
#pragma unroll
        for (int nt = 0; nt < 4; nt++) {
            int colg = col0 + n0w + nt * 8 + cc;
#pragma unroll
            for (int h = 0; h < 2; h++) {
                int rg = r0g + h * 8;
                if (rg >= N_NODES) continue;
                float v0 = acc[mt][nt][h * 2], v1 = acc[mt][nt][h * 2 + 1];
                if (is_y) {
                    *reinterpret_cast<__half2*>(&g_yh[(size_t)rg * 256 + colg]) =
                        __floats2half2_rn(v0, v1);
                } else {
                    *reinterpret_cast<float2*>(&g_z[(size_t)rg * 256 + (colg - 256)]) =
                        make_float2(v0, v1);
                }
            }
        }
    }
}

// ---------------- final: out = segmean(y) + z + bias (half2 gather) ----------------
#define AGG_TILE 64
__global__ void aggregate_final_kernel(const float* __restrict__ br,
                                       float* __restrict__ out) {
    int n  = blockIdx.x;
    int c2 = threadIdx.x;                  // 128 threads, 2 cols each
    __shared__ int ssrc[AGG_TILE];

    float2 z = *reinterpret_cast<const float2*>(&g_z[(size_t)n * 256 + c2 * 2]);
    float2 bias = *reinterpret_cast<const float2*>(&br[c2 * 2]);
    const __half2* yh2 = reinterpret_cast<const __half2*>(g_yh);

    int off0 = g_off[n];
    int off1 = g_off[n + 1];
    float s0 = 0.f, s1 = 0.f;
    for (int base = off0; base < off1; base += AGG_TILE) {
        int cnt = min(AGG_TILE, off1 - base);
        __syncthreads();
        if (c2 < cnt) ssrc[c2] = g_srclist[base + c2];
        __syncthreads();
#pragma unroll 8
        for (int i = 0; i < cnt; i++) {
            float2 v = __half22float2(__ldg(&yh2[(size_t)ssrc[i] * 128 + c2]));
            s0 += v.x; s1 += v.y;
        }
    }
    float inv = 1.0f / fmaxf((float)(off1 - off0), 1.0f);
    float2 o = make_float2(s0 * inv + z.x + bias.x, s1 * inv + z.y + bias.y);
    *reinterpret_cast<float2*>(&out[(size_t)n * 256 + c2 * 2]) = o;
}

// ---------------- launch: fork-join DAG ----------------
extern "C" void kernel_launch(void* const* d_in, const int* in_sizes, int n_in,
                              void* d_out, int out_size) {
    const float* x  = (const float*)d_in[0];
    const int*   ei = (const int*)d_in[1];
    const float* Wl = (const float*)d_in[2];
    const float* Wr = (const float*)d_in[3];
    const float* br = (const float*)d_in[4];
    float* out = (float*)d_out;

    cudaFuncSetAttribute(gemm_yz_kernel,
                         cudaFuncAttributeMaxDynamicSharedMemorySize, GEMM_SMEM);

    // fresh per call; capture runs kernel_launch once, replays never re-enter.
    cudaStream_t s1;
    cudaStreamCreateWithFlags(&s1, cudaStreamNonBlocking);
    cudaEvent_t eFork, eJoin;
    cudaEventCreateWithFlags(&eFork, cudaEventDisableTiming);
    cudaEventCreateWithFlags(&eJoin, cudaEventDisableTiming);

    // fork side branch off the (captured) legacy stream
    cudaEventRecord(eFork, 0);
    cudaStreamWaitEvent(s1, eFork, 0);

    // submission order chosen so the GEMM is the 4th kernel launch (ncu -s5
    // empirically profiles the 4th): conv_w, conv_x, zero, GEMM, ...
    conv_w_kernel<<<256, 128, 0, s1>>>(Wl, Wr);                 // 1
    conv_x_kernel<<<N_NODES / 4, 256, 0, s1>>>(x);              // 2
    zero_kernel<<<20, 1024>>>();                                // 3
    gemm_yz_kernel<<<dim3(157, 8), GT, GEMM_SMEM, s1>>>();      // 4 (profiled)
    count_kernel<<<(N_EDGES + 255) / 256, 256>>>(ei);           // 5
    partsum_kernel<<<NB, 256>>>();                              // 6
    scanwrite_kernel<<<NB, 256>>>();                            // 7
    fill_kernel<<<(N_EDGES + 255) / 256, 256>>>(ei);            // 8

    // join, then final fused gather+add
    cudaEventRecord(eJoin, s1);
    cudaStreamWaitEvent(0, eJoin, 0);
    aggregate_final_kernel<<<N_NODES, 128>>>(br, out);          // 9
}

// round 16
// speedup vs baseline: 1.4777x; 1.0484x over previous
#include <cuda_runtime.h>
#include <cuda_bf16.h>
#include <cuda_fp16.h>
#include <cstdint>

#define N_NODES 20000
#define N_EDGES 320000
#define D 256
#define NB 79          // ceil(20000/256) scan blocks

// ---------------- scratch (no allocations allowed) ----------------
// A' = [hi(x) | lo(x)] per row: 512 bf16 cols
__device__ __nv_bfloat16 g_Axl[(size_t)N_NODES * 512];
// W' rows 0-255 = Wl rows as [hi|lo]; rows 256-511 = Wr rows as [hi|lo]
__device__ __nv_bfloat16 g_Wyz[512 * 512];
// y = x@Wl^T as fp16 (gather traffic halved), z = x@Wr^T as f32
__device__ __half g_yh[(size_t)N_NODES * 256];
__device__ float  g_z[(size_t)N_NODES * 256];
__device__ int g_count[N_NODES];
__device__ int g_off[N_NODES + 1];
__device__ int g_cursor[N_NODES];    // pre-seeded with offsets by scanwrite
__device__ int g_srclist[N_EDGES];
__device__ int g_bsum[NB];

// ---------------- helpers ----------------
__device__ __forceinline__ uint32_t smem_u32(const void* p) {
    uint32_t a;
    asm("{ .reg .u64 t; cvta.to.shared.u64 t, %1; cvt.u32.u64 %0, t; }"
        : "=r"(a) : "l"(p));
    return a;
}
__device__ __forceinline__ void split_bf16(float v, __nv_bfloat16& hi, __nv_bfloat16& lo) {
    hi = __float2bfloat16(v);
    lo = __float2bfloat16(v - __bfloat162float(hi));
}
__device__ __forceinline__ void cp16(uint32_t dst, const void* src, int srcsz) {
    asm volatile("cp.async.cg.shared.global [%0], [%1], 16, %2;"
                 :: "r"(dst), "l"(src), "r"(srcsz));
}
__device__ __forceinline__ void cp_commit() { asm volatile("cp.async.commit_group;" ::: "memory"); }
__device__ __forceinline__ void cp_wait1()  { asm volatile("cp.async.wait_group 1;" ::: "memory"); }
__device__ __forceinline__ void cp_wait0()  { asm volatile("cp.async.wait_group 0;" ::: "memory"); }

__device__ __forceinline__ void ldm_x4(uint32_t* r, uint32_t addr) {
    asm volatile("ldmatrix.sync.aligned.m8n8.x4.shared.b16 {%0,%1,%2,%3}, [%4];"
                 : "=r"(r[0]), "=r"(r[1]), "=r"(r[2]), "=r"(r[3]) : "r"(addr));
}
__device__ __forceinline__ void mma16816(float* d, const uint32_t* a, const uint32_t* b) {
    asm volatile("mma.sync.aligned.m16n8k16.row.col.f32.bf16.bf16.f32 "
                 "{%0,%1,%2,%3}, {%4,%5,%6,%7}, {%8,%9}, {%0,%1,%2,%3};"
                 : "+f"(d[0]), "+f"(d[1]), "+f"(d[2]), "+f"(d[3])
                 : "r"(a[0]), "r"(a[1]), "r"(a[2]), "r"(a[3]), "r"(b[0]), "r"(b[1]));
}

// per-block dtype sniff: int64-LE with values < 2^31 => first 64 odd words all 0.
__device__ __forceinline__ int block_is64(const int* __restrict__ ei, int* s_nz) {
    int tid = threadIdx.x;
    if (tid == 0) *s_nz = 0;
    __syncthreads();
    if (tid < 64 && ei[2 * tid + 1] != 0) atomicOr(s_nz, 1);
    __syncthreads();
    return (*s_nz == 0);
}

// ---------------- CSR build ----------------
__global__ void zero_kernel() {
    int i = blockIdx.x * 1024 + threadIdx.x;
    if (i < N_NODES) g_count[i] = 0;
}

__global__ void count_kernel(const int* __restrict__ ei) {
    __shared__ int s_nz;
    int is64 = block_is64(ei, &s_nz);
    int e = blockIdx.x * blockDim.x + threadIdx.x;
    if (e < N_EDGES) {
        int dst = is64 ? ei[2 * (N_EDGES + e)] : ei[N_EDGES + e];
        atomicAdd(&g_count[dst], 1);
    }
}

__global__ void partsum_kernel() {
    __shared__ int s[256];
    int tid = threadIdx.x;
    int idx = blockIdx.x * 256 + tid;
    s[tid] = (idx < N_NODES) ? g_count[idx] : 0;
    __syncthreads();
    for (int o = 128; o > 0; o >>= 1) {
        if (tid < o) s[tid] += s[tid + o];
        __syncthreads();
    }
    if (tid == 0) g_bsum[blockIdx.x] = s[0];
}

__global__ void scanwrite_kernel() {
    __shared__ int bs[128];
    __shared__ int sc[256];
    int tid = threadIdx.x;
    int b = blockIdx.x;
    if (tid < 128) bs[tid] = (tid < NB) ? g_bsum[tid] : 0;
    __syncthreads();
    for (int o = 1; o < 128; o <<= 1) {
        int v = (tid < 128 && tid >= o) ? bs[tid - o] : 0;
        __syncthreads();
        if (tid < 128) bs[tid] += v;
        __syncthreads();
    }
    int bp = (b == 0) ? 0 : bs[b - 1];
    int idx = b * 256 + tid;
    int cnt = (idx < N_NODES) ? g_count[idx] : 0;
    sc[tid] = cnt;
    __syncthreads();
    for (int o = 1; o < 256; o <<= 1) {
        int v = (tid >= o) ? sc[tid - o] : 0;
        __syncthreads();
        sc[tid] += v;
        __syncthreads();
    }
    if (idx < N_NODES) {
        int off = bp + sc[tid] - cnt;
        g_off[idx] = off;
        g_cursor[idx] = off;           // absolute slot counters for fill
    }
    if (b == 0 && tid == 0) g_off[N_NODES] = N_EDGES;
}

__global__ void fill_kernel(const int* __restrict__ ei) {
    __shared__ int s_nz;
    int is64 = block_is64(ei, &s_nz);
    int e = blockIdx.x * blockDim.x + threadIdx.x;
    if (e >= N_EDGES) return;
    int src, dst;
    if (is64) { src = ei[2 * e]; dst = ei[2 * (N_EDGES + e)]; }
    else      { src = ei[e];     dst = ei[N_EDGES + e]; }
    int slot = atomicAdd(&g_cursor[dst], 1);   // already absolute
    g_srclist[slot] = src;
}

// ---------------- converters ----------------
// 256 threads = 4 rows/block, float4 loads, 8B packed bf16 stores
__global__ void conv_x_kernel(const float* __restrict__ x) {
    int n  = blockIdx.x * 4 + (threadIdx.x >> 6);
    int c4 = (threadIdx.x & 63) * 4;
    float4 v = *reinterpret_cast<const float4*>(&x[(size_t)n * D + c4]);
    __nv_bfloat16 h[4], l[4];
    split_bf16(v.x, h[0], l[0]); split_bf16(v.y, h[1], l[1]);
    split_bf16(v.z, h[2], l[2]); split_bf16(v.w, h[3], l[3]);
    uint32_t hp0, hp1, lp0, lp1;
    memcpy(&hp0, &h[0], 4); memcpy(&hp1, &h[2], 4);
    memcpy(&lp0, &l[0], 4); memcpy(&lp1, &l[2], 4);
    uint2* basehi = reinterpret_cast<uint2*>(&g_Axl[(size_t)n * 512 + c4]);
    uint2* baselo = reinterpret_cast<uint2*>(&g_Axl[(size_t)n * 512 + 256 + c4]);
    *basehi = make_uint2(hp0, hp1);
    *baselo = make_uint2(lp0, lp1);
}

__global__ void conv_w_kernel(const float* __restrict__ Wl, const float* __restrict__ Wr) {
    int n = blockIdx.x;                    // 0..255
    int c2 = threadIdx.x;                  // 128 threads, 2 cols each
    float2 a = *reinterpret_cast<const float2*>(&Wl[n * D + c2 * 2]);
    float2 b = *reinterpret_cast<const float2*>(&Wr[n * D + c2 * 2]);
    __nv_bfloat16 h0, l0, h1, l1;
    __nv_bfloat162* rl = reinterpret_cast<__nv_bfloat162*>(&g_Wyz[n * 512]);
    __nv_bfloat162* rr = reinterpret_cast<__nv_bfloat162*>(&g_Wyz[(256 + n) * 512]);
    split_bf16(a.x, h0, l0); split_bf16(a.y, h1, l1);
    rl[c2] = __nv_bfloat162(h0, h1); rl[128 + c2] = __nv_bfloat162(l0, l1);
    split_bf16(b.x, h0, l0); split_bf16(b.y, h1, l1);
    rr[c2] = __nv_bfloat162(h0, h1); rr[128 + c2] = __nv_bfloat162(l0, l1);
}

// ---------------- mma.sync bf16 GEMM: [y|z] = x @ [Wl|Wr]^T ----------------
// 3 terms (hi*hi, hi*lo, lo*hi) x 4 K-chunks of 64 = 12 chunks.
// CTA tile 128x64 with FOUR warps (2M x 2N), warp tile 64x32.
// smem traffic/chunk: A 16KB x2 + B 8KB x2 = 48KB (was 64KB with 4Mx2N/8w)
// — R13 ncu showed the kernel exactly at the smem-BW bound (548 cyc/chunk),
// so -25% smem reads is a direct speedup.
#define GT 128
#define SM_A(b)   ((b) * 24576)
#define SM_B(b)   ((b) * 24576 + 16384)
#define GEMM_SMEM 49152

extern __shared__ char sm_dyn[];

__device__ __forceinline__ void stage_chunk(uint32_t sb, int b, int Acol, int Wcol, int kc,
                                            int row0, int col0, int tid) {
    uint32_t smA = sb + SM_A(b), smB = sb + SM_B(b);
    const char* Abase = (const char*)g_Axl;
    const char* Bbase = (const char*)g_Wyz;
    // A: 128 rows x 8 chunks = 1024 units (8 iters x 128 threads)
#pragma unroll
    for (int it = 0; it < 8; it++) {
        int u = it * GT + tid;
        int r  = u >> 3;
        int ck = u & 7;
        uint32_t swo = (uint32_t)(r * 8 + (ck ^ (r & 7))) * 16;
        int grow = row0 + r;
        int ok = (grow < N_NODES);
        const char* asrc = Abase + ((size_t)(ok ? grow : 0) * 512 + Acol + kc + ck * 8) * 2;
        cp16(smA + swo, asrc, ok ? 16 : 0);
    }
    // B: 64 rows x 8 chunks = 512 units (4 iters x 128 threads)
#pragma unroll
    for (int it = 0; it < 4; it++) {
        int u = it * GT + tid;
        int r  = u >> 3;                    // 0..63
        int ck = u & 7;
        uint32_t swo = (uint32_t)(r * 8 + (ck ^ (r & 7))) * 16;
        const char* bsrc = Bbase + ((size_t)(col0 + r) * 512 + Wcol + kc + ck * 8) * 2;
        cp16(smB + swo, bsrc, 16);
    }
    cp_commit();
}

__global__ void __launch_bounds__(GT, 4)
gemm_yz_kernel() {
    uint32_t sb = smem_u32(sm_dyn);
    int tid  = threadIdx.x;
    int wid  = tid >> 5;                 // 0..3
    int lane = tid & 31;
    int row0 = blockIdx.x * 128;
    int col0 = blockIdx.y * 64;          // by 0-3 -> y cols; 4-7 -> z cols
    int m0w  = (wid & 1) * 64;           // 2 warps along M, warp tile 64
    int n0w  = (wid >> 1) * 32;          // 2 warps along N, warp tile 32

    float acc[4][4][4];
#pragma unroll
    for (int mt = 0; mt < 4; mt++)
#pragma unroll
        for (int nt = 0; nt < 4; nt++)
#pragma unroll
            for (int j = 0; j < 4; j++) acc[mt][nt][j] = 0.f;

    int a_m  = m0w + (lane & 15);
    int a_kh = (lane >> 4);
    int b_n  = n0w + (lane & 7) + ((lane >> 4) & 1) * 8;
    int b_kh = (lane >> 3) & 1;

    const int CH = 12;
#pragma unroll 1
    for (int c = 0; c <= CH; c++) {
        if (c < CH) {
            int p  = c >> 2;                 // term 0,1,2
            int kc = (c & 3) * 64;
            int Ac = (p == 2) ? 256 : 0;     // lo A only in term 2
            int Wc = (p == 1) ? 256 : 0;     // lo W only in term 1
            stage_chunk(sb, c & 1, Ac, Wc, kc, row0, col0, tid);
        }
        if (c == 0) continue;
        int b = (c - 1) & 1;
        if (c < CH) cp_wait1(); else cp_wait0();
        __syncthreads();

        uint32_t smA = sb + SM_A(b), smB = sb + SM_B(b);
#pragma unroll
        for (int ks = 0; ks < 4; ks++) {
            uint32_t afrag[4][4], bfrag[4][4];
            int ka = ks * 2 + a_kh;
            int kb = ks * 2 + b_kh;
#pragma unroll
            for (int mt = 0; mt < 4; mt++) {          // 64-row A slab (proven R7 path)
                int m = a_m + mt * 16;
                ldm_x4(afrag[mt], smA + (uint32_t)(m * 8 + (ka ^ (m & 7))) * 16);
            }
#pragma unroll
            for (int np = 0; np < 2; np++) {
                int n = b_n + np * 16;
                uint32_t r4[4];
                ldm_x4(r4, smB + (uint32_t)(n * 8 + (kb ^ (n & 7))) * 16);
                bfrag[np * 2][0]     = r4[0]; bfrag[np * 2][1]     = r4[1];
                bfrag[np * 2 + 1][0] = r4[2]; bfrag[np * 2 + 1][1] = r4[3];
            }
#pragma unroll
            for (int mt = 0; mt < 4; mt++)
#pragma unroll
                for (int nt = 0; nt < 4; nt++)
                    mma16816(acc[mt][nt], afrag[mt], bfrag[nt]);
        }
        __syncthreads();
    }

    // epilogue: y cols -> fp16 g_yh, z cols -> f32 g_z
    int cr = lane >> 2;
    int cc = (lane & 3) * 2;
    bool is_y = (col0 < 256);
#pragma unroll
    for (int mt = 0; mt < 4; mt++) {
        int r0g = row0 + m0w + mt * 16 + cr;
#pragma unroll
        for (int nt = 0; nt < 4; nt++) {
            int colg = col0 + n0w + nt * 8 + cc;
#pragma unroll
            for (int h = 0; h < 2; h++) {
                int rg = r0g + h * 8;
                if (rg >= N_NODES) continue;
                float v0 = acc[mt][nt][h * 2], v1 = acc[mt][nt][h * 2 + 1];
                if (is_y) {
                    *reinterpret_cast<__half2*>(&g_yh[(size_t)rg * 256 + colg]) =
                        __floats2half2_rn(v0, v1);
                } else {
                    *reinterpret_cast<float2*>(&g_z[(size_t)rg * 256 + (colg - 256)]) =
                        make_float2(v0, v1);
                }
            }
        }
    }
}

// ---------------- final: out = segmean(y) + z + bias (half2 gather) ----------------
#define AGG_TILE 64
__global__ void aggregate_final_kernel(const float* __restrict__ br,
                                       float* __restrict__ out) {
    int n  = blockIdx.x;
    int c2 = threadIdx.x;                  // 128 threads, 2 cols each
    __shared__ int ssrc[AGG_TILE];

    float2 z = *reinterpret_cast<const float2*>(&g_z[(size_t)n * 256 + c2 * 2]);
    float2 bias = *reinterpret_cast<const float2*>(&br[c2 * 2]);
    const __half2* yh2 = reinterpret_cast<const __half2*>(g_yh);

    int off0 = g_off[n];
    int off1 = g_off[n + 1];
    float s0 = 0.f, s1 = 0.f;
    for (int base = off0; base < off1; base += AGG_TILE) {
        int cnt = min(AGG_TILE, off1 - base);
        __syncthreads();
        if (c2 < cnt) ssrc[c2] = g_srclist[base + c2];
        __syncthreads();
#pragma unroll 8
        for (int i = 0; i < cnt; i++) {
            float2 v = __half22float2(__ldg(&yh2[(size_t)ssrc[i] * 128 + c2]));
            s0 += v.x; s1 += v.y;
        }
    }
    float inv = 1.0f / fmaxf((float)(off1 - off0), 1.0f);
    float2 o = make_float2(s0 * inv + z.x + bias.x, s1 * inv + z.y + bias.y);
    *reinterpret_cast<float2*>(&out[(size_t)n * 256 + c2 * 2]) = o;
}

// ---------------- launch: fork-join DAG (R13-proven footprint) ----------------
extern "C" void kernel_launch(void* const* d_in, const int* in_sizes, int n_in,
                              void* d_out, int out_size) {
    const float* x  = (const float*)d_in[0];
    const int*   ei = (const int*)d_in[1];
    const float* Wl = (const float*)d_in[2];
    const float* Wr = (const float*)d_in[3];
    const float* br = (const float*)d_in[4];
    float* out = (float*)d_out;

    cudaFuncSetAttribute(gemm_yz_kernel,
                         cudaFuncAttributeMaxDynamicSharedMemorySize, GEMM_SMEM);

    // fresh per call; capture runs kernel_launch once, replays never re-enter.
    cudaStream_t s1;
    cudaStreamCreateWithFlags(&s1, cudaStreamNonBlocking);
    cudaEvent_t eFork, eJoin;
    cudaEventCreateWithFlags(&eFork, cudaEventDisableTiming);
    cudaEventCreateWithFlags(&eJoin, cudaEventDisableTiming);

    // fork side branch off the (captured) legacy stream
    cudaEventRecord(eFork, 0);
    cudaStreamWaitEvent(s1, eFork, 0);

    // side branch: W/x conversion + full GEMM (no CSR dep); gemm is the
    // 4th submitted launch so ncu profiles it.
    conv_w_kernel<<<256, 128, 0, s1>>>(Wl, Wr);                 // 1
    conv_x_kernel<<<N_NODES / 4, 256, 0, s1>>>(x);              // 2
    zero_kernel<<<20, 1024>>>();                                // 3 (main)
    gemm_yz_kernel<<<dim3(157, 8), GT, GEMM_SMEM, s1>>>();      // 4 (profiled)

    // main branch: CSR build (atomic-bound; overlaps conv+GEMM)
    count_kernel<<<(N_EDGES + 255) / 256, 256>>>(ei);           // 5
    partsum_kernel<<<NB, 256>>>();                              // 6
    scanwrite_kernel<<<NB, 256>>>();                            // 7
    fill_kernel<<<(N_EDGES + 255) / 256, 256>>>(ei);            // 8

    // join, then final fused gather + z + bias
    cudaEventRecord(eJoin, s1);
    cudaStreamWaitEvent(0, eJoin, 0);
    aggregate_final_kernel<<<N_NODES, 128>>>(br, out);          // 9
}

// round 17
// speedup vs baseline: 1.5662x; 1.0599x over previous
#include <cuda_runtime.h>
#include <cuda_bf16.h>
#include <cuda_fp16.h>
#include <cstdint>

#define N_NODES 20000
#define N_EDGES 320000
#define D 256
#define NB 79          // ceil(20000/256) scan blocks

// ---------------- scratch (no allocations allowed) ----------------
// A' = [hi(x) | lo(x)] per row: 512 bf16 cols
__device__ __nv_bfloat16 g_Axl[(size_t)N_NODES * 512];
// W' rows 0-255 = Wl rows as [hi|lo]; rows 256-511 = Wr rows as [hi|lo]
__device__ __nv_bfloat16 g_Wyz[512 * 512];
// y = x@Wl^T as fp16 (gather traffic halved), z = x@Wr^T as f32
__device__ __half g_yh[(size_t)N_NODES * 256];
__device__ float  g_z[(size_t)N_NODES * 256];
__device__ int g_count[N_NODES];
__device__ int g_off[N_NODES + 1];
__device__ int g_cursor[N_NODES];    // pre-seeded with offsets by scanwrite
__device__ int g_srclist[N_EDGES];
__device__ int g_bsum[NB];

// ---------------- helpers ----------------
__device__ __forceinline__ uint32_t smem_u32(const void* p) {
    uint32_t a;
    asm("{ .reg .u64 t; cvta.to.shared.u64 t, %1; cvt.u32.u64 %0, t; }"
        : "=r"(a) : "l"(p));
    return a;
}
__device__ __forceinline__ void split_bf16(float v, __nv_bfloat16& hi, __nv_bfloat16& lo) {
    hi = __float2bfloat16(v);
    lo = __float2bfloat16(v - __bfloat162float(hi));
}
__device__ __forceinline__ void cp16(uint32_t dst, const void* src, int srcsz) {
    asm volatile("cp.async.cg.shared.global [%0], [%1], 16, %2;"
                 :: "r"(dst), "l"(src), "r"(srcsz));
}
__device__ __forceinline__ void cp_commit() { asm volatile("cp.async.commit_group;" ::: "memory"); }
__device__ __forceinline__ void cp_wait1()  { asm volatile("cp.async.wait_group 1;" ::: "memory"); }
__device__ __forceinline__ void cp_wait0()  { asm volatile("cp.async.wait_group 0;" ::: "memory"); }

__device__ __forceinline__ void ldm_x4(uint32_t* r, uint32_t addr) {
    asm volatile("ldmatrix.sync.aligned.m8n8.x4.shared.b16 {%0,%1,%2,%3}, [%4];"
                 : "=r"(r[0]), "=r"(r[1]), "=r"(r[2]), "=r"(r[3]) : "r"(addr));
}
__device__ __forceinline__ void mma16816(float* d, const uint32_t* a, const uint32_t* b) {
    asm volatile("mma.sync.aligned.m16n8k16.row.col.f32.bf16.bf16.f32 "
                 "{%0,%1,%2,%3}, {%4,%5,%6,%7}, {%8,%9}, {%0,%1,%2,%3};"
                 : "+f"(d[0]), "+f"(d[1]), "+f"(d[2]), "+f"(d[3])
                 : "r"(a[0]), "r"(a[1]), "r"(a[2]), "r"(a[3]), "r"(b[0]), "r"(b[1]));
}

// per-block dtype sniff: int64-LE with values < 2^31 => first 64 odd words all 0.
__device__ __forceinline__ int block_is64(const int* __restrict__ ei, int* s_nz) {
    int tid = threadIdx.x;
    if (tid == 0) *s_nz = 0;
    __syncthreads();
    if (tid < 64 && ei[2 * tid + 1] != 0) atomicOr(s_nz, 1);
    __syncthreads();
    return (*s_nz == 0);
}

// ---------------- CSR build ----------------
__global__ void zero_kernel() {
    int i = blockIdx.x * 1024 + threadIdx.x;
    if (i < N_NODES) g_count[i] = 0;
}

__global__ void count_kernel(const int* __restrict__ ei) {
    __shared__ int s_nz;
    int is64 = block_is64(ei, &s_nz);
    int e = blockIdx.x * blockDim.x + threadIdx.x;
    if (e < N_EDGES) {
        int dst = is64 ? ei[2 * (N_EDGES + e)] : ei[N_EDGES + e];
        atomicAdd(&g_count[dst], 1);
    }
}

__global__ void partsum_kernel() {
    __shared__ int s[256];
    int tid = threadIdx.x;
    int idx = blockIdx.x * 256 + tid;
    s[tid] = (idx < N_NODES) ? g_count[idx] : 0;
    __syncthreads();
    for (int o = 128; o > 0; o >>= 1) {
        if (tid < o) s[tid] += s[tid + o];
        __syncthreads();
    }
    if (tid == 0) g_bsum[blockIdx.x] = s[0];
}

__global__ void scanwrite_kernel() {
    __shared__ int bs[128];
    __shared__ int sc[256];
    int tid = threadIdx.x;
    int b = blockIdx.x;
    if (tid < 128) bs[tid] = (tid < NB) ? g_bsum[tid] : 0;
    __syncthreads();
    for (int o = 1; o < 128; o <<= 1) {
        int v = (tid < 128 && tid >= o) ? bs[tid - o] : 0;
        __syncthreads();
        if (tid < 128) bs[tid] += v;
        __syncthreads();
    }
    int bp = (b == 0) ? 0 : bs[b - 1];
    int idx = b * 256 + tid;
    int cnt = (idx < N_NODES) ? g_count[idx] : 0;
    sc[tid] = cnt;
    __syncthreads();
    for (int o = 1; o < 256; o <<= 1) {
        int v = (tid >= o) ? sc[tid - o] : 0;
        __syncthreads();
        sc[tid] += v;
        __syncthreads();
    }
    if (idx < N_NODES) {
        int off = bp + sc[tid] - cnt;
        g_off[idx] = off;
        g_cursor[idx] = off;           // absolute slot counters for fill
    }
    if (b == 0 && tid == 0) g_off[N_NODES] = N_EDGES;
}

__global__ void fill_kernel(const int* __restrict__ ei) {
    __shared__ int s_nz;
    int is64 = block_is64(ei, &s_nz);
    int e = blockIdx.x * blockDim.x + threadIdx.x;
    if (e >= N_EDGES) return;
    int src, dst;
    if (is64) { src = ei[2 * e]; dst = ei[2 * (N_EDGES + e)]; }
    else      { src = ei[e];     dst = ei[N_EDGES + e]; }
    int slot = atomicAdd(&g_cursor[dst], 1);   // already absolute
    g_srclist[slot] = src;
}

// ---------------- converters ----------------
// 256 threads = 4 rows/block, float4 loads, 8B packed bf16 stores.
// base: block offset so the grid can be split across two streams.
__global__ void conv_x_kernel(const float* __restrict__ x, int base) {
    int n  = (blockIdx.x + base) * 4 + (threadIdx.x >> 6);
    int c4 = (threadIdx.x & 63) * 4;
    float4 v = *reinterpret_cast<const float4*>(&x[(size_t)n * D + c4]);
    __nv_bfloat16 h[4], l[4];
    split_bf16(v.x, h[0], l[0]); split_bf16(v.y, h[1], l[1]);
    split_bf16(v.z, h[2], l[2]); split_bf16(v.w, h[3], l[3]);
    uint32_t hp0, hp1, lp0, lp1;
    memcpy(&hp0, &h[0], 4); memcpy(&hp1, &h[2], 4);
    memcpy(&lp0, &l[0], 4); memcpy(&lp1, &l[2], 4);
    uint2* basehi = reinterpret_cast<uint2*>(&g_Axl[(size_t)n * 512 + c4]);
    uint2* baselo = reinterpret_cast<uint2*>(&g_Axl[(size_t)n * 512 + 256 + c4]);
    *basehi = make_uint2(hp0, hp1);
    *baselo = make_uint2(lp0, lp1);
}

__global__ void conv_w_kernel(const float* __restrict__ Wl, const float* __restrict__ Wr) {
    int n = blockIdx.x;                    // 0..255
    int c2 = threadIdx.x;                  // 128 threads, 2 cols each
    float2 a = *reinterpret_cast<const float2*>(&Wl[n * D + c2 * 2]);
    float2 b = *reinterpret_cast<const float2*>(&Wr[n * D + c2 * 2]);
    __nv_bfloat16 h0, l0, h1, l1;
    __nv_bfloat162* rl = reinterpret_cast<__nv_bfloat162*>(&g_Wyz[n * 512]);
    __nv_bfloat162* rr = reinterpret_cast<__nv_bfloat162*>(&g_Wyz[(256 + n) * 512]);
    split_bf16(a.x, h0, l0); split_bf16(a.y, h1, l1);
    rl[c2] = __nv_bfloat162(h0, h1); rl[128 + c2] = __nv_bfloat162(l0, l1);
    split_bf16(b.x, h0, l0); split_bf16(b.y, h1, l1);
    rr[c2] = __nv_bfloat162(h0, h1); rr[128 + c2] = __nv_bfloat162(l0, l1);
}

// ---------------- mma.sync bf16 GEMM (R16-proven, unchanged) ----------------
// [y|z] = x @ [Wl|Wr]^T; 3 terms x 4 K-chunks of 64 = 12 chunks.
// CTA tile 128x64, 4 warps (2M x 2N), warp tile 64x32.
#define GT 128
#define SM_A(b)   ((b) * 24576)
#define SM_B(b)   ((b) * 24576 + 16384)
#define GEMM_SMEM 49152

extern __shared__ char sm_dyn[];

__device__ __forceinline__ void stage_chunk(uint32_t sb, int b, int Acol, int Wcol, int kc,
                                            int row0, int col0, int tid) {
    uint32_t smA = sb + SM_A(b), smB = sb + SM_B(b);
    const char* Abase = (const char*)g_Axl;
    const char* Bbase = (const char*)g_Wyz;
#pragma unroll
    for (int it = 0; it < 8; it++) {
        int u = it * GT + tid;
        int r  = u >> 3;
        int ck = u & 7;
        uint32_t swo = (uint32_t)(r * 8 + (ck ^ (r & 7))) * 16;
        int grow = row0 + r;
        int ok = (grow < N_NODES);
        const char* asrc = Abase + ((size_t)(ok ? grow : 0) * 512 + Acol + kc + ck * 8) * 2;
        cp16(smA + swo, asrc, ok ? 16 : 0);
    }
#pragma unroll
    for (int it = 0; it < 4; it++) {
        int u = it * GT + tid;
        int r  = u >> 3;                    // 0..63
        int ck = u & 7;
        uint32_t swo = (uint32_t)(r * 8 + (ck ^ (r & 7))) * 16;
        const char* bsrc = Bbase + ((size_t)(col0 + r) * 512 + Wcol + kc + ck * 8) * 2;
        cp16(smB + swo, bsrc, 16);
    }
    cp_commit();
}

__global__ void __launch_bounds__(GT, 4)
gemm_yz_kernel() {
    uint32_t sb = smem_u32(sm_dyn);
    int tid  = threadIdx.x;
    int wid  = tid >> 5;                 // 0..3
    int lane = tid & 31;
    int row0 = blockIdx.x * 128;
    int col0 = blockIdx.y * 64;          // by 0-3 -> y cols; 4-7 -> z cols
    int m0w  = (wid & 1) * 64;
    int n0w  = (wid >> 1) * 32;

    float acc[4][4][4];
#pragma unroll
    for (int mt = 0; mt < 4; mt++)
#pragma unroll
        for (int nt = 0; nt < 4; nt++)
#pragma unroll
            for (int j = 0; j < 4; j++) acc[mt][nt][j] = 0.f;

    int a_m  = m0w + (lane & 15);
    int a_kh = (lane >> 4);
    int b_n  = n0w + (lane & 7) + ((lane >> 4) & 1) * 8;
    int b_kh = (lane >> 3) & 1;

    const int CH = 12;
#pragma unroll 1
    for (int c = 0; c <= CH; c++) {
        if (c < CH) {
            int p  = c >> 2;
            int kc = (c & 3) * 64;
            int Ac = (p == 2) ? 256 : 0;
            int Wc = (p == 1) ? 256 : 0;
            stage_chunk(sb, c & 1, Ac, Wc, kc, row0, col0, tid);
        }
        if (c == 0) continue;
        int b = (c - 1) & 1;
        if (c < CH) cp_wait1(); else cp_wait0();
        __syncthreads();

        uint32_t smA = sb + SM_A(b), smB = sb + SM_B(b);
#pragma unroll
        for (int ks = 0; ks < 4; ks++) {
            uint32_t afrag[4][4], bfrag[4][4];
            int ka = ks * 2 + a_kh;
            int kb = ks * 2 + b_kh;
#pragma unroll
            for (int mt = 0; mt < 4; mt++) {
                int m = a_m + mt * 16;
                ldm_x4(afrag[mt], smA + (uint32_t)(m * 8 + (ka ^ (m & 7))) * 16);
            }
#pragma unroll
            for (int np = 0; np < 2; np++) {
                int n = b_n + np * 16;
                uint32_t r4[4];
                ldm_x4(r4, smB + (uint32_t)(n * 8 + (kb ^ (n & 7))) * 16);
                bfrag[np * 2][0]     = r4[0]; bfrag[np * 2][1]     = r4[1];
                bfrag[np * 2 + 1][0] = r4[2]; bfrag[np * 2 + 1][1] = r4[3];
            }
#pragma unroll
            for (int mt = 0; mt < 4; mt++)
#pragma unroll
                for (int nt = 0; nt < 4; nt++)
                    mma16816(acc[mt][nt], afrag[mt], bfrag[nt]);
        }
        __syncthreads();
    }

    int cr = lane >> 2;
    int cc = (lane & 3) * 2;
    bool is_y = (col0 < 256);
#pragma unroll
    for (int mt = 0; mt < 4; mt++) {
        int r0g = row0 + m0w + mt * 16 + cr;
#pragma unroll
        for (int nt = 0; nt < 4; nt++) {
            int colg = col0 + n0w + nt * 8 + cc;
#pragma unroll
            for (int h = 0; h < 2; h++) {
                int rg = r0g + h * 8;
                if (rg >= N_NODES) continue;
                float v0 = acc[mt][nt][h * 2], v1 = acc[mt][nt][h * 2 + 1];
                if (is_y) {
                    *reinterpret_cast<__half2*>(&g_yh[(size_t)rg * 256 + colg]) =
                        __floats2half2_rn(v0, v1);
                } else {
                    *reinterpret_cast<float2*>(&g_z[(size_t)rg * 256 + (colg - 256)]) =
                        make_float2(v0, v1);
                }
            }
        }
    }
}

// ---------------- final: warp-per-node gather, no smem/barriers ----------------
// One warp per node; lane owns 8 cols (one uint4 = 16B of fp16 per edge).
// src indices: one coalesced srclist load per 32 edges + shfl broadcast.
__device__ __forceinline__ void acc_add(float* a, uint4 v) {
    const __half2* h = reinterpret_cast<const __half2*>(&v);
#pragma unroll
    for (int j = 0; j < 4; j++) {
        float2 f = __half22float2(h[j]);
        a[2 * j]     += f.x;
        a[2 * j + 1] += f.y;
    }
}

__global__ void aggregate_final_kernel(const float* __restrict__ br,
                                       float* __restrict__ out) {
    int n    = (blockIdx.x * 256 + threadIdx.x) >> 5;   // node = global warp id
    int lane = threadIdx.x & 31;
    if (n >= N_NODES) return;

    const uint4* y4 = reinterpret_cast<const uint4*>(g_yh);   // 32 uint4 per row
    float acc[8];
#pragma unroll
    for (int j = 0; j < 8; j++) acc[j] = 0.f;

    int off0 = g_off[n];
    int off1 = g_off[n + 1];
    for (int base = off0; base < off1; base += 32) {
        int cnt = min(32, off1 - base);
        int s = (base + lane < off1) ? g_srclist[base + lane] : 0;
        int i = 0;
        for (; i + 4 <= cnt; i += 4) {
            int s0 = __shfl_sync(0xffffffffu, s, i);
            int s1 = __shfl_sync(0xffffffffu, s, i + 1);
            int s2 = __shfl_sync(0xffffffffu, s, i + 2);
            int s3 = __shfl_sync(0xffffffffu, s, i + 3);
            uint4 v0 = __ldg(&y4[(size_t)s0 * 32 + lane]);
            uint4 v1 = __ldg(&y4[(size_t)s1 * 32 + lane]);
            uint4 v2 = __ldg(&y4[(size_t)s2 * 32 + lane]);
            uint4 v3 = __ldg(&y4[(size_t)s3 * 32 + lane]);
            acc_add(acc, v0); acc_add(acc, v1); acc_add(acc, v2); acc_add(acc, v3);
        }
        for (; i < cnt; i++) {
            int ss = __shfl_sync(0xffffffffu, s, i);
            uint4 v = __ldg(&y4[(size_t)ss * 32 + lane]);
            acc_add(acc, v);
        }
    }

    float inv = 1.0f / fmaxf((float)(off1 - off0), 1.0f);
    const float4* z4 = reinterpret_cast<const float4*>(g_z);  // 64 float4 per row
    const float4* b4 = reinterpret_cast<const float4*>(br);
    float4 za = __ldg(&z4[(size_t)n * 64 + lane * 2]);
    float4 zb = __ldg(&z4[(size_t)n * 64 + lane * 2 + 1]);
    float4 ba = __ldg(&b4[lane * 2]);
    float4 bb = __ldg(&b4[lane * 2 + 1]);
    float4 o0, o1;
    o0.x = acc[0] * inv + za.x + ba.x;  o0.y = acc[1] * inv + za.y + ba.y;
    o0.z = acc[2] * inv + za.z + ba.z;  o0.w = acc[3] * inv + za.w + ba.w;
    o1.x = acc[4] * inv + zb.x + bb.x;  o1.y = acc[5] * inv + zb.y + bb.y;
    o1.z = acc[6] * inv + zb.z + bb.z;  o1.w = acc[7] * inv + zb.w + bb.w;
    float4* ov = reinterpret_cast<float4*>(out);
    ov[(size_t)n * 64 + lane * 2]     = o0;
    ov[(size_t)n * 64 + lane * 2 + 1] = o1;
}

// ---------------- launch: fork-join DAG (one extra stream, proven clean) ----------------
extern "C" void kernel_launch(void* const* d_in, const int* in_sizes, int n_in,
                              void* d_out, int out_size) {
    const float* x  = (const float*)d_in[0];
    const int*   ei = (const int*)d_in[1];
    const float* Wl = (const float*)d_in[2];
    const float* Wr = (const float*)d_in[3];
    const float* br = (const float*)d_in[4];
    float* out = (float*)d_out;

    cudaFuncSetAttribute(gemm_yz_kernel,
                         cudaFuncAttributeMaxDynamicSharedMemorySize, GEMM_SMEM);

    // fresh per call; capture runs kernel_launch once, replays never re-enter.
    cudaStream_t s1;
    cudaStreamCreateWithFlags(&s1, cudaStreamNonBlocking);
    cudaEvent_t eFork, eCX, eJoin;
    cudaEventCreateWithFlags(&eFork, cudaEventDisableTiming);
    cudaEventCreateWithFlags(&eCX, cudaEventDisableTiming);
    cudaEventCreateWithFlags(&eJoin, cudaEventDisableTiming);

    cudaEventRecord(eFork, 0);
    cudaStreamWaitEvent(s1, eFork, 0);

    const int XB = N_NODES / 4;          // 5000 conv_x blocks total

    // side branch on s1; main stream takes half of conv_x so the gemm's
    // critical path is max(conv_w + half, half) instead of conv_w + full.
    conv_w_kernel<<<256, 128, 0, s1>>>(Wl, Wr);                   // 1
    conv_x_kernel<<<XB / 2, 256, 0, s1>>>(x, 0);                  // 2
    conv_x_kernel<<<XB - XB / 2, 256>>>(x, XB / 2);               // 3 (main)
    cudaEventRecord(eCX, 0);
    cudaStreamWaitEvent(s1, eCX, 0);
    gemm_yz_kernel<<<dim3(157, 8), GT, GEMM_SMEM, s1>>>();        // 4 (profiled)

    // main branch: CSR build (overlaps GEMM)
    zero_kernel<<<20, 1024>>>();                                  // 5
    count_kernel<<<(N_EDGES + 255) / 256, 256>>>(ei);             // 6
    partsum_kernel<<<NB, 256>>>();                                // 7
    scanwrite_kernel<<<NB, 256>>>();                              // 8
    fill_kernel<<<(N_EDGES + 255) / 256, 256>>>(ei);              // 9

    // join, then final fused gather + z + bias (warp-per-node)
    cudaEventRecord(eJoin, s1);
    cudaStreamWaitEvent(0, eJoin, 0);
    aggregate_final_kernel<<<(N_NODES * 32 + 255) / 256, 256>>>(br, out);  // 10
}